// round 1
// baseline (speedup 1.0000x reference)
#include <cuda_runtime.h>
#include <math.h>
#include <stdint.h>

// Problem shape (fixed)
#define BB 4
#define TT 2048
#define CC 1024
#define HH 16
#define HD 64
#define MM (BB * TT)     // 8192 rows
#define C3 (3 * CC)      // 3072

// Scratch (device globals — allocation-free per harness rules)
__device__ float g_qkv[(size_t)MM * C3];   // 96 MB
__device__ float g_y[(size_t)MM * CC];     // 32 MB

// ---------------------------------------------------------------------------
// SGEMM: C[M,N] = A[M,K] @ B[K,N] + bias[N]
// BM=BN=128, BK=8, 256 threads, 8x8 register tile per thread.
// M,N,K all multiples of tile sizes for this problem -> no bounds checks.
// ---------------------------------------------------------------------------
__global__ __launch_bounds__(256)
void sgemm_bias(const float* __restrict__ A, const float* __restrict__ B,
                const float* __restrict__ bias, float* __restrict__ C,
                int M, int N, int K)
{
    __shared__ float As[8][128];   // transposed A tile: As[k][m]
    __shared__ float Bs[8][128];   // Bs[k][n]

    const int tid  = threadIdx.x;
    const int row0 = blockIdx.y * 128;
    const int col0 = blockIdx.x * 128;

    // A tile load mapping: 128 rows x 8 cols, one float4 per thread along K.
    const int arow = tid & 127;          // 0..127
    const int acol = (tid >> 7) * 4;     // 0 or 4
    // B tile load mapping: 8 rows x 128 cols, one float4 per thread along N.
    const int brow = tid >> 5;           // 0..7
    const int bcol = (tid & 31) * 4;     // 0..124

    const int ty = tid >> 4;             // 0..15
    const int tx = tid & 15;             // 0..15

    float acc[8][8];
    #pragma unroll
    for (int i = 0; i < 8; i++)
        #pragma unroll
        for (int j = 0; j < 8; j++) acc[i][j] = 0.0f;

    const float* Aptr = A + (size_t)(row0 + arow) * K + acol;
    const float* Bptr = B + (size_t)brow * N + col0 + bcol;

    for (int k0 = 0; k0 < K; k0 += 8) {
        float4 a4 = *(const float4*)(Aptr + k0);
        float4 b4 = *(const float4*)(Bptr + (size_t)k0 * N);
        As[acol + 0][arow] = a4.x;
        As[acol + 1][arow] = a4.y;
        As[acol + 2][arow] = a4.z;
        As[acol + 3][arow] = a4.w;
        *(float4*)&Bs[brow][bcol] = b4;
        __syncthreads();

        #pragma unroll
        for (int kk = 0; kk < 8; kk++) {
            float ar[8], br[8];
            *(float4*)(ar + 0) = *(const float4*)&As[kk][ty * 8 + 0];
            *(float4*)(ar + 4) = *(const float4*)&As[kk][ty * 8 + 4];
            *(float4*)(br + 0) = *(const float4*)&Bs[kk][tx * 8 + 0];
            *(float4*)(br + 4) = *(const float4*)&Bs[kk][tx * 8 + 4];
            #pragma unroll
            for (int i = 0; i < 8; i++)
                #pragma unroll
                for (int j = 0; j < 8; j++)
                    acc[i][j] += ar[i] * br[j];
        }
        __syncthreads();
    }

    // Epilogue: add bias, store float4s.
    #pragma unroll
    for (int i = 0; i < 8; i++) {
        const int r = row0 + ty * 8 + i;
        float* crow = C + (size_t)r * N + col0 + tx * 8;
        #pragma unroll
        for (int j = 0; j < 8; j += 4) {
            float4 o;
            o.x = acc[i][j + 0] + bias[col0 + tx * 8 + j + 0];
            o.y = acc[i][j + 1] + bias[col0 + tx * 8 + j + 1];
            o.z = acc[i][j + 2] + bias[col0 + tx * 8 + j + 2];
            o.w = acc[i][j + 3] + bias[col0 + tx * 8 + j + 3];
            *(float4*)(crow + j) = o;
        }
    }
}

// ---------------------------------------------------------------------------
// Flash attention (fp32, causal). One block = one (b, h, 64-query tile).
// 256 threads; each thread owns a 4x4 tile of S / O in a 16x16 thread grid.
// Q,K stored transposed [d][row] with stride 65 (scalar reads: Q broadcast
// conflict-free, K 2-way). V natural [k][c] stride 64 (float4). P staged
// [q][k] stride 65 (scalar broadcast reads conflict-free).
// ---------------------------------------------------------------------------
#define BQ 64
#define BKV 64
#define PSTR 65

__global__ __launch_bounds__(256)
void flash_attn(const float* __restrict__ qkv, float* __restrict__ y)
{
    extern __shared__ float sm[];
    float* Qs = sm;                    // 64*65
    float* Ks = Qs + 64 * PSTR;        // 64*65
    float* Ps = Ks + 64 * PSTR;        // 64*65
    float* Vs = Ps + 64 * PSTR;        // 64*64 (offset 12480 floats, 16B aligned)

    const int tid = threadIdx.x;
    const int b = blockIdx.z, h = blockIdx.y;
    // Reverse q-tile order: heaviest (most causal tiles) blocks launch first.
    const int q0 = (gridDim.x - 1 - blockIdx.x) * BQ;

    const float* base = qkv + (size_t)b * TT * C3 + h * HD;
    const float* Qg = base;
    const float* Kg = base + CC;
    const float* Vg = base + 2 * CC;

    // Load Q tile, transposed into Qs[d][m].
    #pragma unroll
    for (int it = 0; it < 4; it++) {
        int idx = tid + it * 256;            // 0..1023
        int r = idx >> 4;                    // 0..63
        int dc = (idx & 15) << 2;            // 0..60
        float4 q4 = *(const float4*)(Qg + (size_t)(q0 + r) * C3 + dc);
        Qs[(dc + 0) * PSTR + r] = q4.x;
        Qs[(dc + 1) * PSTR + r] = q4.y;
        Qs[(dc + 2) * PSTR + r] = q4.z;
        Qs[(dc + 3) * PSTR + r] = q4.w;
    }

    const int tr = tid >> 4;   // 0..15 : query-row group (4 rows)
    const int tc = tid & 15;   // 0..15 : col group (4 cols)

    float mi[4], li[4], acc[4][4];
    #pragma unroll
    for (int i = 0; i < 4; i++) {
        mi[i] = -1e30f; li[i] = 0.0f;
        #pragma unroll
        for (int j = 0; j < 4; j++) acc[i][j] = 0.0f;
    }

    const int ntile = (q0 >> 6) + 1;
    for (int jt = 0; jt < ntile; jt++) {
        const int k0 = jt << 6;
        __syncthreads();   // protect prev-iter reads of Ks/Vs/Ps

        // Load K (transposed) and V (natural) tiles.
        #pragma unroll
        for (int it = 0; it < 4; it++) {
            int idx = tid + it * 256;
            int r = idx >> 4;
            int dc = (idx & 15) << 2;
            float4 k4 = *(const float4*)(Kg + (size_t)(k0 + r) * C3 + dc);
            Ks[(dc + 0) * PSTR + r] = k4.x;
            Ks[(dc + 1) * PSTR + r] = k4.y;
            Ks[(dc + 2) * PSTR + r] = k4.z;
            Ks[(dc + 3) * PSTR + r] = k4.w;
            float4 v4 = *(const float4*)(Vg + (size_t)(k0 + r) * C3 + dc);
            *(float4*)(Vs + r * 64 + dc) = v4;
        }
        __syncthreads();

        // S = Q K^T (4x4 per thread)
        float s[4][4];
        #pragma unroll
        for (int i = 0; i < 4; i++)
            #pragma unroll
            for (int j = 0; j < 4; j++) s[i][j] = 0.0f;

        #pragma unroll 8
        for (int kk = 0; kk < 64; kk++) {
            float qr[4], kr[4];
            #pragma unroll
            for (int i = 0; i < 4; i++) qr[i] = Qs[kk * PSTR + tr * 4 + i];
            #pragma unroll
            for (int j = 0; j < 4; j++) kr[j] = Ks[kk * PSTR + tc * 4 + j];
            #pragma unroll
            for (int i = 0; i < 4; i++)
                #pragma unroll
                for (int j = 0; j < 4; j++)
                    s[i][j] += qr[i] * kr[j];
        }

        const float scale = 0.125f;   // 1/sqrt(64)
        const bool diag = (k0 == q0);
        #pragma unroll
        for (int i = 0; i < 4; i++)
            #pragma unroll
            for (int j = 0; j < 4; j++) {
                float v = s[i][j] * scale;
                if (diag && (tc * 4 + j) > (tr * 4 + i)) v = -1e30f;
                s[i][j] = v;
            }

        // Online softmax update (row stats reduced over 16 lanes sharing tr).
        #pragma unroll
        for (int i = 0; i < 4; i++) {
            float mx = fmaxf(fmaxf(s[i][0], s[i][1]), fmaxf(s[i][2], s[i][3]));
            #pragma unroll
            for (int off = 8; off; off >>= 1)
                mx = fmaxf(mx, __shfl_xor_sync(0xffffffffu, mx, off));
            float mnew = fmaxf(mi[i], mx);
            float alpha = __expf(mi[i] - mnew);
            float sum = 0.0f;
            #pragma unroll
            for (int j = 0; j < 4; j++) {
                float p = __expf(s[i][j] - mnew);
                s[i][j] = p;
                sum += p;
            }
            #pragma unroll
            for (int off = 8; off; off >>= 1)
                sum += __shfl_xor_sync(0xffffffffu, sum, off);
            li[i] = li[i] * alpha + sum;
            mi[i] = mnew;
            #pragma unroll
            for (int j = 0; j < 4; j++) acc[i][j] *= alpha;
        }

        // Stage P to shared.
        #pragma unroll
        for (int i = 0; i < 4; i++)
            #pragma unroll
            for (int j = 0; j < 4; j++)
                Ps[(tr * 4 + i) * PSTR + tc * 4 + j] = s[i][j];
        __syncthreads();

        // O += P @ V
        #pragma unroll 8
        for (int kk = 0; kk < 64; kk++) {
            float pr[4];
            #pragma unroll
            for (int i = 0; i < 4; i++) pr[i] = Ps[(tr * 4 + i) * PSTR + kk];
            float4 vv = *(const float4*)(Vs + kk * 64 + tc * 4);
            float vr[4] = {vv.x, vv.y, vv.z, vv.w};
            #pragma unroll
            for (int i = 0; i < 4; i++)
                #pragma unroll
                for (int j = 0; j < 4; j++)
                    acc[i][j] += pr[i] * vr[j];
        }
    }

    // Epilogue: normalize and write y[b, q, h*HD + c]  (layout [B,T,C])
    #pragma unroll
    for (int i = 0; i < 4; i++) {
        float inv = 1.0f / li[i];
        float4 o;
        o.x = acc[i][0] * inv;
        o.y = acc[i][1] * inv;
        o.z = acc[i][2] * inv;
        o.w = acc[i][3] * inv;
        size_t row = (size_t)b * TT + q0 + tr * 4 + i;
        *(float4*)(y + row * CC + h * HD + tc * 4) = o;
    }
}

// ---------------------------------------------------------------------------
// Launch
// ---------------------------------------------------------------------------
extern "C" void kernel_launch(void* const* d_in, const int* in_sizes, int n_in,
                              void* d_out, int out_size)
{
    const float* x     = (const float*)d_in[0];   // [4,2048,1024]
    const float* Wqkv  = (const float*)d_in[1];   // [1024,3072]
    const float* bqkv  = (const float*)d_in[2];   // [3072]
    const float* Wproj = (const float*)d_in[3];   // [1024,1024]
    const float* bproj = (const float*)d_in[4];   // [1024]
    float* out = (float*)d_out;                   // [4,2048,1024]

    float *qkv, *ybuf;
    cudaGetSymbolAddress((void**)&qkv, g_qkv);
    cudaGetSymbolAddress((void**)&ybuf, g_y);

    const int smem_attn = (3 * 64 * PSTR + 64 * 64) * sizeof(float);  // 66304 B
    cudaFuncSetAttribute(flash_attn, cudaFuncAttributeMaxDynamicSharedMemorySize,
                         smem_attn);

    // 1) QKV projection: [8192,1024] @ [1024,3072]
    sgemm_bias<<<dim3(C3 / 128, MM / 128), 256>>>(x, Wqkv, bqkv, qkv, MM, C3, CC);

    // 2) Causal flash attention -> ybuf [8192,1024]
    flash_attn<<<dim3(TT / BQ, HH, BB), 256, smem_attn>>>(qkv, ybuf);

    // 3) Output projection: [8192,1024] @ [1024,1024]
    sgemm_bias<<<dim3(CC / 128, MM / 128), 256>>>(ybuf, Wproj, bproj, out, MM, CC, CC);
}

// round 3
// speedup vs baseline: 1.7017x; 1.7017x over previous
#include <cuda_runtime.h>
#include <math.h>
#include <stdint.h>

// Problem shape (fixed)
#define BB 4
#define TT 2048
#define CC 1024
#define HH 16
#define HD 64
#define MM (BB * TT)     // 8192 rows
#define C3 (3 * CC)      // 3072

// Scratch (device globals — allocation-free per harness rules)
__device__ float g_qkv[(size_t)MM * C3];   // 96 MB
__device__ float g_y[(size_t)MM * CC];     // 32 MB

// ---------------------------------------------------------------------------
// PTX helpers (baseline sm_80+ features only — NO tcgen05: harness PTX target
// is compute_103 (no 'a'), which rejects accelerated-arch instructions).
// ---------------------------------------------------------------------------
__device__ __forceinline__ uint32_t smem_u32(const void* p) {
    uint32_t a;
    asm("{ .reg .u64 t; cvta.to.shared.u64 t, %1; cvt.u32.u64 %0, t; }"
        : "=r"(a) : "l"(p));
    return a;
}

#define CP_ASYNC16(dst, src) \
    asm volatile("cp.async.cg.shared.global [%0], [%1], 16;\n" \
                 :: "r"(dst), "l"(src) : "memory")
#define CP_COMMIT()  asm volatile("cp.async.commit_group;\n" ::: "memory")
#define CP_WAIT1()   asm volatile("cp.async.wait_group 1;\n" ::: "memory")

__device__ __forceinline__ uint32_t f2tf32(float f) {
    uint32_t r;
    asm("cvt.rna.tf32.f32 %0, %1;" : "=r"(r) : "f"(f));
    return r;
}

__device__ __forceinline__ void mma_tf32(float c[4], const uint32_t a[4],
                                         uint32_t b0, uint32_t b1) {
    asm volatile(
        "mma.sync.aligned.m16n8k8.row.col.f32.tf32.tf32.f32 "
        "{%0,%1,%2,%3}, {%4,%5,%6,%7}, {%8,%9}, {%0,%1,%2,%3};"
        : "+f"(c[0]), "+f"(c[1]), "+f"(c[2]), "+f"(c[3])
        : "r"(a[0]), "r"(a[1]), "r"(a[2]), "r"(a[3]), "r"(b0), "r"(b1));
}

// ---------------------------------------------------------------------------
// TF32 mma.sync GEMM: C[M,N] = A[M,K] @ B[K,N] + bias[N]
// CTA 128x128x16, 256 threads (8 warps: 4M x 2N), warp tile 32x64.
// A smem [m][k] stride 20 (bank-bijective A-frag reads),
// B smem [k][n] stride 136 (bank-bijective B-frag reads).
// cp.async double-buffered. fp32 accumulators.
// ---------------------------------------------------------------------------
#define BM 128
#define BN 128
#define BK 16
#define ASTR 20    // floats per A row
#define BSTR 136   // floats per B row

__global__ __launch_bounds__(256)
void gemm_tf32mma(const float* __restrict__ A, const float* __restrict__ B,
                  const float* __restrict__ bias, float* __restrict__ C,
                  int M, int N, int K)
{
    __shared__ float As[2][BM * ASTR];   // 2 x 10240 B
    __shared__ float Bs[2][BK * BSTR];   // 2 x  8704 B

    const int tid  = threadIdx.x;
    const int wid  = tid >> 5;
    const int lane = tid & 31;
    const int quad = lane >> 2;   // 0..7
    const int tq   = lane & 3;    // 0..3
    const int warpM = wid & 3;    // 0..3
    const int warpN = wid >> 2;   // 0..1
    const int row0 = blockIdx.y * BM;
    const int col0 = blockIdx.x * BN;

    float acc[2][8][4];
    #pragma unroll
    for (int mt = 0; mt < 2; mt++)
        #pragma unroll
        for (int nt = 0; nt < 8; nt++)
            #pragma unroll
            for (int j = 0; j < 4; j++) acc[mt][nt][j] = 0.0f;

    uint32_t sA[2] = { smem_u32(As[0]), smem_u32(As[1]) };
    uint32_t sB[2] = { smem_u32(Bs[0]), smem_u32(Bs[1]) };

    // Per-thread load slots (2 A chunks + 2 B chunks of 16B per kt).
    const int aRow0 = tid >> 2;            // id = tid
    const int aKc0  = (tid & 3) << 2;
    const int aRow1 = (tid + 256) >> 2;    // id = tid + 256
    const int aKc1  = ((tid + 256) & 3) << 2;
    const int bRow0 = tid >> 5;
    const int bNc0  = (tid & 31) << 2;
    const int bRow1 = (tid + 256) >> 5;
    const int bNc1  = ((tid + 256) & 31) << 2;

    auto load_tile = [&](int kt) {
        const int s = kt & 1;
        const int k0 = kt * BK;
        CP_ASYNC16(sA[s] + (uint32_t)(aRow0 * (ASTR * 4) + aKc0 * 4),
                   A + (size_t)(row0 + aRow0) * K + k0 + aKc0);
        CP_ASYNC16(sA[s] + (uint32_t)(aRow1 * (ASTR * 4) + aKc1 * 4),
                   A + (size_t)(row0 + aRow1) * K + k0 + aKc1);
        CP_ASYNC16(sB[s] + (uint32_t)(bRow0 * (BSTR * 4) + bNc0 * 4),
                   B + (size_t)(k0 + bRow0) * N + col0 + bNc0);
        CP_ASYNC16(sB[s] + (uint32_t)(bRow1 * (BSTR * 4) + bNc1 * 4),
                   B + (size_t)(k0 + bRow1) * N + col0 + bNc1);
    };

    const int NKT = K / BK;
    load_tile(0); CP_COMMIT();
    load_tile(1); CP_COMMIT();

    for (int kt = 0; kt < NKT; kt++) {
        CP_WAIT1();
        __syncthreads();
        const float* as = As[kt & 1];
        const float* bs = Bs[kt & 1];

        #pragma unroll
        for (int ks = 0; ks < 2; ks++) {
            uint32_t af[2][4];
            #pragma unroll
            for (int mt = 0; mt < 2; mt++) {
                const int mb = warpM * 32 + mt * 16 + quad;
                const int c  = ks * 8 + tq;
                af[mt][0] = f2tf32(as[mb * ASTR + c]);
                af[mt][1] = f2tf32(as[(mb + 8) * ASTR + c]);
                af[mt][2] = f2tf32(as[mb * ASTR + c + 4]);
                af[mt][3] = f2tf32(as[(mb + 8) * ASTR + c + 4]);
            }
            #pragma unroll
            for (int nt = 0; nt < 8; nt++) {
                const int n0 = warpN * 64 + nt * 8 + quad;
                uint32_t b0 = f2tf32(bs[(ks * 8 + tq) * BSTR + n0]);
                uint32_t b1 = f2tf32(bs[(ks * 8 + tq + 4) * BSTR + n0]);
                mma_tf32(acc[0][nt], af[0], b0, b1);
                mma_tf32(acc[1][nt], af[1], b0, b1);
            }
        }
        __syncthreads();
        if (kt + 2 < NKT) load_tile(kt + 2);
        CP_COMMIT();
    }

    // Epilogue: c0/c1 -> (row, 2tq..2tq+1), c2/c3 -> (row+8, ...)
    #pragma unroll
    for (int mt = 0; mt < 2; mt++) {
        #pragma unroll
        for (int half = 0; half < 2; half++) {
            const int row = row0 + warpM * 32 + mt * 16 + quad + half * 8;
            float* crow = C + (size_t)row * N;
            #pragma unroll
            for (int nt = 0; nt < 8; nt++) {
                const int col = col0 + warpN * 64 + nt * 8 + 2 * tq;
                float2 v;
                v.x = acc[mt][nt][half * 2 + 0] + __ldg(bias + col);
                v.y = acc[mt][nt][half * 2 + 1] + __ldg(bias + col + 1);
                *(float2*)(crow + col) = v;
            }
        }
    }
}

// ---------------------------------------------------------------------------
// Flash attention (fp32, causal) — unchanged from R1 baseline (passing).
// ---------------------------------------------------------------------------
#define BQ 64
#define PSTR 65

__global__ __launch_bounds__(256)
void flash_attn(const float* __restrict__ qkv, float* __restrict__ y)
{
    extern __shared__ float sm[];
    float* Qs = sm;
    float* Ks = Qs + 64 * PSTR;
    float* Ps = Ks + 64 * PSTR;
    float* Vs = Ps + 64 * PSTR;

    const int tid = threadIdx.x;
    const int b = blockIdx.z, h = blockIdx.y;
    const int q0 = (gridDim.x - 1 - blockIdx.x) * BQ;

    const float* base = qkv + (size_t)b * TT * C3 + h * HD;
    const float* Qg = base;
    const float* Kg = base + CC;
    const float* Vg = base + 2 * CC;

    #pragma unroll
    for (int it = 0; it < 4; it++) {
        int idx = tid + it * 256;
        int r = idx >> 4;
        int dc = (idx & 15) << 2;
        float4 q4 = *(const float4*)(Qg + (size_t)(q0 + r) * C3 + dc);
        Qs[(dc + 0) * PSTR + r] = q4.x;
        Qs[(dc + 1) * PSTR + r] = q4.y;
        Qs[(dc + 2) * PSTR + r] = q4.z;
        Qs[(dc + 3) * PSTR + r] = q4.w;
    }

    const int tr = tid >> 4;
    const int tc = tid & 15;

    float mi[4], li[4], acc[4][4];
    #pragma unroll
    for (int i = 0; i < 4; i++) {
        mi[i] = -1e30f; li[i] = 0.0f;
        #pragma unroll
        for (int j = 0; j < 4; j++) acc[i][j] = 0.0f;
    }

    const int ntile = (q0 >> 6) + 1;
    for (int jt = 0; jt < ntile; jt++) {
        const int k0 = jt << 6;
        __syncthreads();

        #pragma unroll
        for (int it = 0; it < 4; it++) {
            int idx = tid + it * 256;
            int r = idx >> 4;
            int dc = (idx & 15) << 2;
            float4 k4 = *(const float4*)(Kg + (size_t)(k0 + r) * C3 + dc);
            Ks[(dc + 0) * PSTR + r] = k4.x;
            Ks[(dc + 1) * PSTR + r] = k4.y;
            Ks[(dc + 2) * PSTR + r] = k4.z;
            Ks[(dc + 3) * PSTR + r] = k4.w;
            float4 v4 = *(const float4*)(Vg + (size_t)(k0 + r) * C3 + dc);
            *(float4*)(Vs + r * 64 + dc) = v4;
        }
        __syncthreads();

        float s[4][4];
        #pragma unroll
        for (int i = 0; i < 4; i++)
            #pragma unroll
            for (int j = 0; j < 4; j++) s[i][j] = 0.0f;

        #pragma unroll 8
        for (int kk = 0; kk < 64; kk++) {
            float qr[4], kr[4];
            #pragma unroll
            for (int i = 0; i < 4; i++) qr[i] = Qs[kk * PSTR + tr * 4 + i];
            #pragma unroll
            for (int j = 0; j < 4; j++) kr[j] = Ks[kk * PSTR + tc * 4 + j];
            #pragma unroll
            for (int i = 0; i < 4; i++)
                #pragma unroll
                for (int j = 0; j < 4; j++)
                    s[i][j] += qr[i] * kr[j];
        }

        const float scale = 0.125f;
        const bool diag = (k0 == q0);
        #pragma unroll
        for (int i = 0; i < 4; i++)
            #pragma unroll
            for (int j = 0; j < 4; j++) {
                float v = s[i][j] * scale;
                if (diag && (tc * 4 + j) > (tr * 4 + i)) v = -1e30f;
                s[i][j] = v;
            }

        #pragma unroll
        for (int i = 0; i < 4; i++) {
            float mx = fmaxf(fmaxf(s[i][0], s[i][1]), fmaxf(s[i][2], s[i][3]));
            #pragma unroll
            for (int off = 8; off; off >>= 1)
                mx = fmaxf(mx, __shfl_xor_sync(0xffffffffu, mx, off));
            float mnew = fmaxf(mi[i], mx);
            float alpha = __expf(mi[i] - mnew);
            float sum = 0.0f;
            #pragma unroll
            for (int j = 0; j < 4; j++) {
                float p = __expf(s[i][j] - mnew);
                s[i][j] = p;
                sum += p;
            }
            #pragma unroll
            for (int off = 8; off; off >>= 1)
                sum += __shfl_xor_sync(0xffffffffu, sum, off);
            li[i] = li[i] * alpha + sum;
            mi[i] = mnew;
            #pragma unroll
            for (int j = 0; j < 4; j++) acc[i][j] *= alpha;
        }

        #pragma unroll
        for (int i = 0; i < 4; i++)
            #pragma unroll
            for (int j = 0; j < 4; j++)
                Ps[(tr * 4 + i) * PSTR + tc * 4 + j] = s[i][j];
        __syncthreads();

        #pragma unroll 8
        for (int kk = 0; kk < 64; kk++) {
            float pr[4];
            #pragma unroll
            for (int i = 0; i < 4; i++) pr[i] = Ps[(tr * 4 + i) * PSTR + kk];
            float4 vv = *(const float4*)(Vs + kk * 64 + tc * 4);
            float vr[4] = {vv.x, vv.y, vv.z, vv.w};
            #pragma unroll
            for (int i = 0; i < 4; i++)
                #pragma unroll
                for (int j = 0; j < 4; j++)
                    acc[i][j] += pr[i] * vr[j];
        }
    }

    #pragma unroll
    for (int i = 0; i < 4; i++) {
        float inv = 1.0f / li[i];
        float4 o;
        o.x = acc[i][0] * inv;
        o.y = acc[i][1] * inv;
        o.z = acc[i][2] * inv;
        o.w = acc[i][3] * inv;
        size_t row = (size_t)b * TT + q0 + tr * 4 + i;
        *(float4*)(y + row * CC + h * HD + tc * 4) = o;
    }
}

// ---------------------------------------------------------------------------
// Launch
// ---------------------------------------------------------------------------
extern "C" void kernel_launch(void* const* d_in, const int* in_sizes, int n_in,
                              void* d_out, int out_size)
{
    const float* x     = (const float*)d_in[0];   // [4,2048,1024]
    const float* Wqkv  = (const float*)d_in[1];   // [1024,3072] (K-major rows = .col B)
    const float* bqkv  = (const float*)d_in[2];   // [3072]
    const float* Wproj = (const float*)d_in[3];   // [1024,1024]
    const float* bproj = (const float*)d_in[4];   // [1024]
    float* out = (float*)d_out;                   // [4,2048,1024]

    float *qkv, *ybuf;
    cudaGetSymbolAddress((void**)&qkv, g_qkv);
    cudaGetSymbolAddress((void**)&ybuf, g_y);

    const int smem_attn = (3 * 64 * PSTR + 64 * 64) * sizeof(float);
    cudaFuncSetAttribute(flash_attn, cudaFuncAttributeMaxDynamicSharedMemorySize,
                         smem_attn);

    // 1) QKV projection: [8192,1024] @ [1024,3072] (tf32 mma.sync)
    gemm_tf32mma<<<dim3(C3 / BN, MM / BM), 256>>>(x, Wqkv, bqkv, qkv, MM, C3, CC);

    // 2) Causal flash attention -> ybuf [8192,1024]
    flash_attn<<<dim3(TT / BQ, HH, BB), 256, smem_attn>>>(qkv, ybuf);

    // 3) Output projection: [8192,1024] @ [1024,1024]
    gemm_tf32mma<<<dim3(CC / BN, MM / BM), 256>>>(ybuf, Wproj, bproj, out, MM, CC, CC);
}

// round 4
// speedup vs baseline: 2.9497x; 1.7334x over previous
#include <cuda_runtime.h>
#include <math.h>
#include <stdint.h>

// Problem shape (fixed)
#define BB 4
#define TT 2048
#define CC 1024
#define HH 16
#define HD 64
#define MM (BB * TT)     // 8192 rows
#define C3 (3 * CC)      // 3072

// Scratch (device globals — allocation-free per harness rules)
__device__ float g_qkv[(size_t)MM * C3];   // 96 MB
__device__ float g_y[(size_t)MM * CC];     // 32 MB

// ---------------------------------------------------------------------------
// PTX helpers (baseline sm_80+ only: harness PTX target is compute_103,
// which rejects tcgen05/accelerated-arch instructions).
// ---------------------------------------------------------------------------
__device__ __forceinline__ uint32_t smem_u32(const void* p) {
    uint32_t a;
    asm("{ .reg .u64 t; cvta.to.shared.u64 t, %1; cvt.u32.u64 %0, t; }"
        : "=r"(a) : "l"(p));
    return a;
}

#define CP_ASYNC16(dst, src) \
    asm volatile("cp.async.cg.shared.global [%0], [%1], 16;\n" \
                 :: "r"(dst), "l"(src) : "memory")
#define CP_COMMIT()  asm volatile("cp.async.commit_group;\n" ::: "memory")
#define CP_WAIT1()   asm volatile("cp.async.wait_group 1;\n" ::: "memory")

__device__ __forceinline__ uint32_t f2tf32(float f) {
    uint32_t r;
    asm("cvt.rna.tf32.f32 %0, %1;" : "=r"(r) : "f"(f));
    return r;
}

__device__ __forceinline__ void mma_tf32(float c[4], const uint32_t a[4],
                                         uint32_t b0, uint32_t b1) {
    asm volatile(
        "mma.sync.aligned.m16n8k8.row.col.f32.tf32.tf32.f32 "
        "{%0,%1,%2,%3}, {%4,%5,%6,%7}, {%8,%9}, {%0,%1,%2,%3};"
        : "+f"(c[0]), "+f"(c[1]), "+f"(c[2]), "+f"(c[3])
        : "r"(a[0]), "r"(a[1]), "r"(a[2]), "r"(a[3]), "r"(b0), "r"(b1));
}

// ---------------------------------------------------------------------------
// TF32 mma.sync GEMM (unchanged from R3 — passing, 378us on QKV).
// ---------------------------------------------------------------------------
#define BM 128
#define BN 128
#define BK 16
#define ASTR 20
#define BSTR 136

__global__ __launch_bounds__(256)
void gemm_tf32mma(const float* __restrict__ A, const float* __restrict__ B,
                  const float* __restrict__ bias, float* __restrict__ C,
                  int M, int N, int K)
{
    __shared__ float As[2][BM * ASTR];
    __shared__ float Bs[2][BK * BSTR];

    const int tid  = threadIdx.x;
    const int wid  = tid >> 5;
    const int lane = tid & 31;
    const int quad = lane >> 2;
    const int tq   = lane & 3;
    const int warpM = wid & 3;
    const int warpN = wid >> 2;
    const int row0 = blockIdx.y * BM;
    const int col0 = blockIdx.x * BN;

    float acc[2][8][4];
    #pragma unroll
    for (int mt = 0; mt < 2; mt++)
        #pragma unroll
        for (int nt = 0; nt < 8; nt++)
            #pragma unroll
            for (int j = 0; j < 4; j++) acc[mt][nt][j] = 0.0f;

    uint32_t sA[2] = { smem_u32(As[0]), smem_u32(As[1]) };
    uint32_t sB[2] = { smem_u32(Bs[0]), smem_u32(Bs[1]) };

    const int aRow0 = tid >> 2;
    const int aKc0  = (tid & 3) << 2;
    const int aRow1 = (tid + 256) >> 2;
    const int aKc1  = ((tid + 256) & 3) << 2;
    const int bRow0 = tid >> 5;
    const int bNc0  = (tid & 31) << 2;
    const int bRow1 = (tid + 256) >> 5;
    const int bNc1  = ((tid + 256) & 31) << 2;

    auto load_tile = [&](int kt) {
        const int s = kt & 1;
        const int k0 = kt * BK;
        CP_ASYNC16(sA[s] + (uint32_t)(aRow0 * (ASTR * 4) + aKc0 * 4),
                   A + (size_t)(row0 + aRow0) * K + k0 + aKc0);
        CP_ASYNC16(sA[s] + (uint32_t)(aRow1 * (ASTR * 4) + aKc1 * 4),
                   A + (size_t)(row0 + aRow1) * K + k0 + aKc1);
        CP_ASYNC16(sB[s] + (uint32_t)(bRow0 * (BSTR * 4) + bNc0 * 4),
                   B + (size_t)(k0 + bRow0) * N + col0 + bNc0);
        CP_ASYNC16(sB[s] + (uint32_t)(bRow1 * (BSTR * 4) + bNc1 * 4),
                   B + (size_t)(k0 + bRow1) * N + col0 + bNc1);
    };

    const int NKT = K / BK;
    load_tile(0); CP_COMMIT();
    load_tile(1); CP_COMMIT();

    for (int kt = 0; kt < NKT; kt++) {
        CP_WAIT1();
        __syncthreads();
        const float* as = As[kt & 1];
        const float* bs = Bs[kt & 1];

        #pragma unroll
        for (int ks = 0; ks < 2; ks++) {
            uint32_t af[2][4];
            #pragma unroll
            for (int mt = 0; mt < 2; mt++) {
                const int mb = warpM * 32 + mt * 16 + quad;
                const int c  = ks * 8 + tq;
                af[mt][0] = f2tf32(as[mb * ASTR + c]);
                af[mt][1] = f2tf32(as[(mb + 8) * ASTR + c]);
                af[mt][2] = f2tf32(as[mb * ASTR + c + 4]);
                af[mt][3] = f2tf32(as[(mb + 8) * ASTR + c + 4]);
            }
            #pragma unroll
            for (int nt = 0; nt < 8; nt++) {
                const int n0 = warpN * 64 + nt * 8 + quad;
                uint32_t b0 = f2tf32(bs[(ks * 8 + tq) * BSTR + n0]);
                uint32_t b1 = f2tf32(bs[(ks * 8 + tq + 4) * BSTR + n0]);
                mma_tf32(acc[0][nt], af[0], b0, b1);
                mma_tf32(acc[1][nt], af[1], b0, b1);
            }
        }
        __syncthreads();
        if (kt + 2 < NKT) load_tile(kt + 2);
        CP_COMMIT();
    }

    #pragma unroll
    for (int mt = 0; mt < 2; mt++) {
        #pragma unroll
        for (int half = 0; half < 2; half++) {
            const int row = row0 + warpM * 32 + mt * 16 + quad + half * 8;
            float* crow = C + (size_t)row * N;
            #pragma unroll
            for (int nt = 0; nt < 8; nt++) {
                const int col = col0 + warpN * 64 + nt * 8 + 2 * tq;
                float2 v;
                v.x = acc[mt][nt][half * 2 + 0] + __ldg(bias + col);
                v.y = acc[mt][nt][half * 2 + 1] + __ldg(bias + col + 1);
                *(float2*)(crow + col) = v;
            }
        }
    }
}

// ---------------------------------------------------------------------------
// Flash attention with tf32 mma.sync. Block = 128 threads (4 warps), one
// (b, h, 64-query tile). Warp w owns q rows [w*16, w*16+16).
// Smem tiles stride 68: fragment reads (quad*4+tq mod 32) bank-bijective.
// Q/K/V converted to tf32 ONCE at load; frag loads are raw LDS.
// ---------------------------------------------------------------------------
#define FSTR 68
#define BQ 64

__global__ __launch_bounds__(128)
void flash_attn_mma(const float* __restrict__ qkv, float* __restrict__ y)
{
    extern __shared__ float sm[];
    float* Qs = sm;                  // [64][68] tf32 bits
    float* Ks = Qs + 64 * FSTR;
    float* Vs = Ks + 64 * FSTR;
    float* Ps = Vs + 64 * FSTR;

    const int tid  = threadIdx.x;
    const int w    = tid >> 5;
    const int lane = tid & 31;
    const int quad = lane >> 2;
    const int tq   = lane & 3;

    const int b = blockIdx.z, h = blockIdx.y;
    const int q0 = (gridDim.x - 1 - blockIdx.x) * BQ;   // heavy tiles first

    const float* base = qkv + (size_t)b * TT * C3 + h * HD;
    const float* Qg = base;
    const float* Kg = base + CC;
    const float* Vg = base + 2 * CC;

    // Load Q tile (convert to tf32 in smem).
    #pragma unroll
    for (int it = 0; it < 8; it++) {
        int idx = tid + it * 128;           // 0..1023
        int r  = idx >> 4;
        int dc = (idx & 15) << 2;
        float4 v = *(const float4*)(Qg + (size_t)(q0 + r) * C3 + dc);
        float4 o;
        o.x = __uint_as_float(f2tf32(v.x));
        o.y = __uint_as_float(f2tf32(v.y));
        o.z = __uint_as_float(f2tf32(v.z));
        o.w = __uint_as_float(f2tf32(v.w));
        *(float4*)(Qs + r * FSTR + dc) = o;
    }

    const int rowA = w * 16 + quad;        // frag row (also row+8)

    float mi0 = -1e30f, mi1 = -1e30f, li0 = 0.0f, li1 = 0.0f;
    float oacc[8][4];
    #pragma unroll
    for (int nt = 0; nt < 8; nt++)
        #pragma unroll
        for (int j = 0; j < 4; j++) oacc[nt][j] = 0.0f;

    const int ntile = (q0 >> 6) + 1;
    for (int jt = 0; jt < ntile; jt++) {
        const int k0 = jt << 6;
        __syncthreads();   // all prior reads of Ks/Vs done

        // Load K and V tiles (tf32-convert once).
        #pragma unroll
        for (int it = 0; it < 8; it++) {
            int idx = tid + it * 128;
            int r  = idx >> 4;
            int dc = (idx & 15) << 2;
            float4 kv4 = *(const float4*)(Kg + (size_t)(k0 + r) * C3 + dc);
            float4 ko;
            ko.x = __uint_as_float(f2tf32(kv4.x));
            ko.y = __uint_as_float(f2tf32(kv4.y));
            ko.z = __uint_as_float(f2tf32(kv4.z));
            ko.w = __uint_as_float(f2tf32(kv4.w));
            *(float4*)(Ks + r * FSTR + dc) = ko;
            float4 vv4 = *(const float4*)(Vg + (size_t)(k0 + r) * C3 + dc);
            float4 vo;
            vo.x = __uint_as_float(f2tf32(vv4.x));
            vo.y = __uint_as_float(f2tf32(vv4.y));
            vo.z = __uint_as_float(f2tf32(vv4.z));
            vo.w = __uint_as_float(f2tf32(vv4.w));
            *(float4*)(Vs + r * FSTR + dc) = vo;
        }
        __syncthreads();

        // ---- S = Q K^T : warp computes 16x64 ----
        float sacc[8][4];
        #pragma unroll
        for (int nt = 0; nt < 8; nt++)
            #pragma unroll
            for (int j = 0; j < 4; j++) sacc[nt][j] = 0.0f;

        #pragma unroll
        for (int kc = 0; kc < 8; kc++) {
            uint32_t af[4];
            af[0] = __float_as_uint(Qs[rowA * FSTR + kc * 8 + tq]);
            af[1] = __float_as_uint(Qs[(rowA + 8) * FSTR + kc * 8 + tq]);
            af[2] = __float_as_uint(Qs[rowA * FSTR + kc * 8 + tq + 4]);
            af[3] = __float_as_uint(Qs[(rowA + 8) * FSTR + kc * 8 + tq + 4]);
            #pragma unroll
            for (int nt = 0; nt < 8; nt++) {
                uint32_t b0 = __float_as_uint(Ks[(nt * 8 + quad) * FSTR + kc * 8 + tq]);
                uint32_t b1 = __float_as_uint(Ks[(nt * 8 + quad) * FSTR + kc * 8 + tq + 4]);
                mma_tf32(sacc[nt], af, b0, b1);
            }
        }

        // ---- scale + causal mask (diag tile only) ----
        const float scale = 0.125f;
        const bool diag = (jt == ntile - 1);
        #pragma unroll
        for (int nt = 0; nt < 8; nt++) {
            #pragma unroll
            for (int j = 0; j < 4; j++) {
                float v = sacc[nt][j] * scale;
                if (diag) {
                    int c = nt * 8 + 2 * tq + (j & 1);
                    int r = w * 16 + quad + (j >> 1) * 8;
                    if (c > r) v = -1e30f;
                }
                sacc[nt][j] = v;
            }
        }

        // ---- online softmax (rows quad and quad+8; reduce over tq lanes) ----
        float mx0 = -1e30f, mx1 = -1e30f;
        #pragma unroll
        for (int nt = 0; nt < 8; nt++) {
            mx0 = fmaxf(mx0, fmaxf(sacc[nt][0], sacc[nt][1]));
            mx1 = fmaxf(mx1, fmaxf(sacc[nt][2], sacc[nt][3]));
        }
        mx0 = fmaxf(mx0, __shfl_xor_sync(0xffffffffu, mx0, 1));
        mx0 = fmaxf(mx0, __shfl_xor_sync(0xffffffffu, mx0, 2));
        mx1 = fmaxf(mx1, __shfl_xor_sync(0xffffffffu, mx1, 1));
        mx1 = fmaxf(mx1, __shfl_xor_sync(0xffffffffu, mx1, 2));

        float mn0 = fmaxf(mi0, mx0), mn1 = fmaxf(mi1, mx1);
        float al0 = __expf(mi0 - mn0), al1 = __expf(mi1 - mn1);

        float sum0 = 0.0f, sum1 = 0.0f;
        #pragma unroll
        for (int nt = 0; nt < 8; nt++) {
            float p0 = __expf(sacc[nt][0] - mn0);
            float p1 = __expf(sacc[nt][1] - mn0);
            float p2 = __expf(sacc[nt][2] - mn1);
            float p3 = __expf(sacc[nt][3] - mn1);
            sum0 += p0 + p1;
            sum1 += p2 + p3;
            sacc[nt][0] = p0; sacc[nt][1] = p1;
            sacc[nt][2] = p2; sacc[nt][3] = p3;
        }
        sum0 += __shfl_xor_sync(0xffffffffu, sum0, 1);
        sum0 += __shfl_xor_sync(0xffffffffu, sum0, 2);
        sum1 += __shfl_xor_sync(0xffffffffu, sum1, 1);
        sum1 += __shfl_xor_sync(0xffffffffu, sum1, 2);

        li0 = li0 * al0 + sum0;  mi0 = mn0;
        li1 = li1 * al1 + sum1;  mi1 = mn1;
        #pragma unroll
        for (int nt = 0; nt < 8; nt++) {
            oacc[nt][0] *= al0; oacc[nt][1] *= al0;
            oacc[nt][2] *= al1; oacc[nt][3] *= al1;
        }

        // ---- stage P (tf32 bits) into warp-private smem rows ----
        __syncwarp();
        #pragma unroll
        for (int nt = 0; nt < 8; nt++) {
            float2 p01, p23;
            p01.x = __uint_as_float(f2tf32(sacc[nt][0]));
            p01.y = __uint_as_float(f2tf32(sacc[nt][1]));
            p23.x = __uint_as_float(f2tf32(sacc[nt][2]));
            p23.y = __uint_as_float(f2tf32(sacc[nt][3]));
            *(float2*)(Ps + rowA * FSTR + nt * 8 + 2 * tq) = p01;
            *(float2*)(Ps + (rowA + 8) * FSTR + nt * 8 + 2 * tq) = p23;
        }
        __syncwarp();

        // ---- O += P V ----
        #pragma unroll
        for (int kc = 0; kc < 8; kc++) {
            uint32_t af[4];
            af[0] = __float_as_uint(Ps[rowA * FSTR + kc * 8 + tq]);
            af[1] = __float_as_uint(Ps[(rowA + 8) * FSTR + kc * 8 + tq]);
            af[2] = __float_as_uint(Ps[rowA * FSTR + kc * 8 + tq + 4]);
            af[3] = __float_as_uint(Ps[(rowA + 8) * FSTR + kc * 8 + tq + 4]);
            #pragma unroll
            for (int nt = 0; nt < 8; nt++) {
                uint32_t b0 = __float_as_uint(Vs[(kc * 8 + tq) * FSTR + nt * 8 + quad]);
                uint32_t b1 = __float_as_uint(Vs[(kc * 8 + tq + 4) * FSTR + nt * 8 + quad]);
                mma_tf32(oacc[nt], af, b0, b1);
            }
        }
    }

    // ---- epilogue: y[b, q0+row, h*64 + col] ----
    const float inv0 = 1.0f / li0;
    const float inv1 = 1.0f / li1;
    const size_t r0 = (size_t)b * TT + q0 + w * 16 + quad;
    #pragma unroll
    for (int nt = 0; nt < 8; nt++) {
        const int col = h * HD + nt * 8 + 2 * tq;
        float2 v0, v1;
        v0.x = oacc[nt][0] * inv0;  v0.y = oacc[nt][1] * inv0;
        v1.x = oacc[nt][2] * inv1;  v1.y = oacc[nt][3] * inv1;
        *(float2*)(y + r0 * CC + col) = v0;
        *(float2*)(y + (r0 + 8) * CC + col) = v1;
    }
}

// ---------------------------------------------------------------------------
// Launch
// ---------------------------------------------------------------------------
extern "C" void kernel_launch(void* const* d_in, const int* in_sizes, int n_in,
                              void* d_out, int out_size)
{
    const float* x     = (const float*)d_in[0];
    const float* Wqkv  = (const float*)d_in[1];
    const float* bqkv  = (const float*)d_in[2];
    const float* Wproj = (const float*)d_in[3];
    const float* bproj = (const float*)d_in[4];
    float* out = (float*)d_out;

    float *qkv, *ybuf;
    cudaGetSymbolAddress((void**)&qkv, g_qkv);
    cudaGetSymbolAddress((void**)&ybuf, g_y);

    const int smem_attn = 4 * 64 * FSTR * sizeof(float);   // 69632 B
    cudaFuncSetAttribute(flash_attn_mma,
                         cudaFuncAttributeMaxDynamicSharedMemorySize, smem_attn);

    // 1) QKV projection (tf32 mma.sync)
    gemm_tf32mma<<<dim3(C3 / BN, MM / BM), 256>>>(x, Wqkv, bqkv, qkv, MM, C3, CC);

    // 2) Causal flash attention (tf32 mma.sync) -> ybuf
    flash_attn_mma<<<dim3(TT / BQ, HH, BB), 128, smem_attn>>>(qkv, ybuf);

    // 3) Output projection
    gemm_tf32mma<<<dim3(CC / BN, MM / BM), 256>>>(ybuf, Wproj, bproj, out, MM, CC, CC);
}

// round 5
// speedup vs baseline: 3.0272x; 1.0263x over previous
#include <cuda_runtime.h>
#include <math.h>
#include <stdint.h>

// Problem shape (fixed)
#define BB 4
#define TT 2048
#define CC 1024
#define HH 16
#define HD 64
#define MM (BB * TT)     // 8192 rows
#define C3 (3 * CC)      // 3072

// Scratch (device globals — allocation-free per harness rules)
__device__ float g_qkv[(size_t)MM * C3];   // 96 MB (tf32-rounded by QKV gemm)
__device__ float g_y[(size_t)MM * CC];     // 32 MB (tf32-rounded by attention)
__device__ float g_xt[(size_t)MM * CC];    // 32 MB x, tf32-rounded
__device__ float g_wt[(size_t)C3 * CC + (size_t)CC * CC];  // 16 MB weights, tf32-rounded

// ---------------------------------------------------------------------------
// PTX helpers (baseline sm_80+ only: harness PTX target is compute_103,
// which rejects tcgen05/accelerated-arch instructions).
// ---------------------------------------------------------------------------
__device__ __forceinline__ uint32_t smem_u32(const void* p) {
    uint32_t a;
    asm("{ .reg .u64 t; cvta.to.shared.u64 t, %1; cvt.u32.u64 %0, t; }"
        : "=r"(a) : "l"(p));
    return a;
}

#define CP_ASYNC16(dst, src) \
    asm volatile("cp.async.cg.shared.global [%0], [%1], 16;\n" \
                 :: "r"(dst), "l"(src) : "memory")
#define CP_COMMIT()  asm volatile("cp.async.commit_group;\n" ::: "memory")
#define CP_WAIT1()   asm volatile("cp.async.wait_group 1;\n" ::: "memory")

__device__ __forceinline__ uint32_t f2tf32(float f) {
    uint32_t r;
    asm("cvt.rna.tf32.f32 %0, %1;" : "=r"(r) : "f"(f));
    return r;
}
__device__ __forceinline__ float f2tf32f(float f) {
    return __uint_as_float(f2tf32(f));
}

__device__ __forceinline__ void mma_tf32(float c[4], const uint32_t a[4],
                                         uint32_t b0, uint32_t b1) {
    asm volatile(
        "mma.sync.aligned.m16n8k8.row.col.f32.tf32.tf32.f32 "
        "{%0,%1,%2,%3}, {%4,%5,%6,%7}, {%8,%9}, {%0,%1,%2,%3};"
        : "+f"(c[0]), "+f"(c[1]), "+f"(c[2]), "+f"(c[3])
        : "r"(a[0]), "r"(a[1]), "r"(a[2]), "r"(a[3]), "r"(b0), "r"(b1));
}

// ---------------------------------------------------------------------------
// Elementwise tf32 rounding pass (producers not under our control).
// ---------------------------------------------------------------------------
__global__ __launch_bounds__(256)
void conv_tf32(const float* __restrict__ in, float* __restrict__ out, int n4)
{
    int i = blockIdx.x * 256 + threadIdx.x;
    if (i < n4) {
        float4 v = ((const float4*)in)[i];
        float4 o;
        o.x = f2tf32f(v.x); o.y = f2tf32f(v.y);
        o.z = f2tf32f(v.z); o.w = f2tf32f(v.w);
        ((float4*)out)[i] = o;
    }
}

// ---------------------------------------------------------------------------
// TF32 mma.sync GEMM: C = A @ B + bias. Operands MUST be pre-rounded to tf32.
// CTA 128x128x16, 256 threads (8 warps: 4M x 2N), warp tile 32x64.
// ROUND_OUT: round the fp32 result to tf32 before store (for tensors that
// feed a later tf32 mma — saves re-conversion downstream).
// ---------------------------------------------------------------------------
#define BM 128
#define BN 128
#define BK 16
#define ASTR 20
#define BSTR 136

template<bool ROUND_OUT>
__global__ __launch_bounds__(256)
void gemm_tf32mma(const float* __restrict__ A, const float* __restrict__ B,
                  const float* __restrict__ bias, float* __restrict__ C,
                  int M, int N, int K)
{
    __shared__ float As[2][BM * ASTR];
    __shared__ float Bs[2][BK * BSTR];

    const int tid  = threadIdx.x;
    const int wid  = tid >> 5;
    const int lane = tid & 31;
    const int quad = lane >> 2;
    const int tq   = lane & 3;
    const int warpM = wid & 3;
    const int warpN = wid >> 2;
    const int row0 = blockIdx.y * BM;
    const int col0 = blockIdx.x * BN;

    float acc[2][8][4];
    #pragma unroll
    for (int mt = 0; mt < 2; mt++)
        #pragma unroll
        for (int nt = 0; nt < 8; nt++)
            #pragma unroll
            for (int j = 0; j < 4; j++) acc[mt][nt][j] = 0.0f;

    uint32_t sA[2] = { smem_u32(As[0]), smem_u32(As[1]) };
    uint32_t sB[2] = { smem_u32(Bs[0]), smem_u32(Bs[1]) };

    const int aRow0 = tid >> 2;
    const int aKc0  = (tid & 3) << 2;
    const int aRow1 = (tid + 256) >> 2;
    const int aKc1  = ((tid + 256) & 3) << 2;
    const int bRow0 = tid >> 5;
    const int bNc0  = (tid & 31) << 2;
    const int bRow1 = (tid + 256) >> 5;
    const int bNc1  = ((tid + 256) & 31) << 2;

    auto load_tile = [&](int kt) {
        const int s = kt & 1;
        const int k0 = kt * BK;
        CP_ASYNC16(sA[s] + (uint32_t)(aRow0 * (ASTR * 4) + aKc0 * 4),
                   A + (size_t)(row0 + aRow0) * K + k0 + aKc0);
        CP_ASYNC16(sA[s] + (uint32_t)(aRow1 * (ASTR * 4) + aKc1 * 4),
                   A + (size_t)(row0 + aRow1) * K + k0 + aKc1);
        CP_ASYNC16(sB[s] + (uint32_t)(bRow0 * (BSTR * 4) + bNc0 * 4),
                   B + (size_t)(k0 + bRow0) * N + col0 + bNc0);
        CP_ASYNC16(sB[s] + (uint32_t)(bRow1 * (BSTR * 4) + bNc1 * 4),
                   B + (size_t)(k0 + bRow1) * N + col0 + bNc1);
    };

    const int NKT = K / BK;
    load_tile(0); CP_COMMIT();
    load_tile(1); CP_COMMIT();

    for (int kt = 0; kt < NKT; kt++) {
        CP_WAIT1();
        __syncthreads();
        const float* as = As[kt & 1];
        const float* bs = Bs[kt & 1];

        #pragma unroll
        for (int ks = 0; ks < 2; ks++) {
            uint32_t af[2][4];
            #pragma unroll
            for (int mt = 0; mt < 2; mt++) {
                const int mb = warpM * 32 + mt * 16 + quad;
                const int c  = ks * 8 + tq;
                af[mt][0] = __float_as_uint(as[mb * ASTR + c]);
                af[mt][1] = __float_as_uint(as[(mb + 8) * ASTR + c]);
                af[mt][2] = __float_as_uint(as[mb * ASTR + c + 4]);
                af[mt][3] = __float_as_uint(as[(mb + 8) * ASTR + c + 4]);
            }
            #pragma unroll
            for (int nt = 0; nt < 8; nt++) {
                const int n0 = warpN * 64 + nt * 8 + quad;
                uint32_t b0 = __float_as_uint(bs[(ks * 8 + tq) * BSTR + n0]);
                uint32_t b1 = __float_as_uint(bs[(ks * 8 + tq + 4) * BSTR + n0]);
                mma_tf32(acc[0][nt], af[0], b0, b1);
                mma_tf32(acc[1][nt], af[1], b0, b1);
            }
        }
        __syncthreads();
        if (kt + 2 < NKT) load_tile(kt + 2);
        CP_COMMIT();
    }

    #pragma unroll
    for (int mt = 0; mt < 2; mt++) {
        #pragma unroll
        for (int half = 0; half < 2; half++) {
            const int row = row0 + warpM * 32 + mt * 16 + quad + half * 8;
            float* crow = C + (size_t)row * N;
            #pragma unroll
            for (int nt = 0; nt < 8; nt++) {
                const int col = col0 + warpN * 64 + nt * 8 + 2 * tq;
                float2 v;
                v.x = acc[mt][nt][half * 2 + 0] + __ldg(bias + col);
                v.y = acc[mt][nt][half * 2 + 1] + __ldg(bias + col + 1);
                if (ROUND_OUT) { v.x = f2tf32f(v.x); v.y = f2tf32f(v.y); }
                *(float2*)(crow + col) = v;
            }
        }
    }
}

// ---------------------------------------------------------------------------
// Flash attention with tf32 mma.sync. Inputs (qkv) are already tf32-rounded
// by the QKV GEMM epilogue -> raw copies into smem, no cvt in load loop.
// Output ybuf is rounded to tf32 (feeds proj gemm).
// ---------------------------------------------------------------------------
#define FSTR 68
#define BQ 64

__global__ __launch_bounds__(128)
void flash_attn_mma(const float* __restrict__ qkv, float* __restrict__ y)
{
    extern __shared__ float sm[];
    float* Qs = sm;                  // [64][68]
    float* Ks = Qs + 64 * FSTR;
    float* Vs = Ks + 64 * FSTR;
    float* Ps = Vs + 64 * FSTR;

    const int tid  = threadIdx.x;
    const int w    = tid >> 5;
    const int lane = tid & 31;
    const int quad = lane >> 2;
    const int tq   = lane & 3;

    const int b = blockIdx.z, h = blockIdx.y;
    const int q0 = (gridDim.x - 1 - blockIdx.x) * BQ;   // heavy tiles first

    const float* base = qkv + (size_t)b * TT * C3 + h * HD;
    const float* Qg = base;
    const float* Kg = base + CC;
    const float* Vg = base + 2 * CC;

    // Load Q tile (already tf32-rounded).
    #pragma unroll
    for (int it = 0; it < 8; it++) {
        int idx = tid + it * 128;
        int r  = idx >> 4;
        int dc = (idx & 15) << 2;
        *(float4*)(Qs + r * FSTR + dc) =
            *(const float4*)(Qg + (size_t)(q0 + r) * C3 + dc);
    }

    const int rowA = w * 16 + quad;

    float mi0 = -1e30f, mi1 = -1e30f, li0 = 0.0f, li1 = 0.0f;
    float oacc[8][4];
    #pragma unroll
    for (int nt = 0; nt < 8; nt++)
        #pragma unroll
        for (int j = 0; j < 4; j++) oacc[nt][j] = 0.0f;

    const int ntile = (q0 >> 6) + 1;
    for (int jt = 0; jt < ntile; jt++) {
        const int k0 = jt << 6;
        __syncthreads();

        #pragma unroll
        for (int it = 0; it < 8; it++) {
            int idx = tid + it * 128;
            int r  = idx >> 4;
            int dc = (idx & 15) << 2;
            *(float4*)(Ks + r * FSTR + dc) =
                *(const float4*)(Kg + (size_t)(k0 + r) * C3 + dc);
            *(float4*)(Vs + r * FSTR + dc) =
                *(const float4*)(Vg + (size_t)(k0 + r) * C3 + dc);
        }
        __syncthreads();

        // ---- S = Q K^T ----
        float sacc[8][4];
        #pragma unroll
        for (int nt = 0; nt < 8; nt++)
            #pragma unroll
            for (int j = 0; j < 4; j++) sacc[nt][j] = 0.0f;

        #pragma unroll
        for (int kc = 0; kc < 8; kc++) {
            uint32_t af[4];
            af[0] = __float_as_uint(Qs[rowA * FSTR + kc * 8 + tq]);
            af[1] = __float_as_uint(Qs[(rowA + 8) * FSTR + kc * 8 + tq]);
            af[2] = __float_as_uint(Qs[rowA * FSTR + kc * 8 + tq + 4]);
            af[3] = __float_as_uint(Qs[(rowA + 8) * FSTR + kc * 8 + tq + 4]);
            #pragma unroll
            for (int nt = 0; nt < 8; nt++) {
                uint32_t b0 = __float_as_uint(Ks[(nt * 8 + quad) * FSTR + kc * 8 + tq]);
                uint32_t b1 = __float_as_uint(Ks[(nt * 8 + quad) * FSTR + kc * 8 + tq + 4]);
                mma_tf32(sacc[nt], af, b0, b1);
            }
        }

        // ---- scale + causal mask ----
        const float scale = 0.125f;
        const bool diag = (jt == ntile - 1);
        #pragma unroll
        for (int nt = 0; nt < 8; nt++) {
            #pragma unroll
            for (int j = 0; j < 4; j++) {
                float v = sacc[nt][j] * scale;
                if (diag) {
                    int c = nt * 8 + 2 * tq + (j & 1);
                    int r = w * 16 + quad + (j >> 1) * 8;
                    if (c > r) v = -1e30f;
                }
                sacc[nt][j] = v;
            }
        }

        // ---- online softmax ----
        float mx0 = -1e30f, mx1 = -1e30f;
        #pragma unroll
        for (int nt = 0; nt < 8; nt++) {
            mx0 = fmaxf(mx0, fmaxf(sacc[nt][0], sacc[nt][1]));
            mx1 = fmaxf(mx1, fmaxf(sacc[nt][2], sacc[nt][3]));
        }
        mx0 = fmaxf(mx0, __shfl_xor_sync(0xffffffffu, mx0, 1));
        mx0 = fmaxf(mx0, __shfl_xor_sync(0xffffffffu, mx0, 2));
        mx1 = fmaxf(mx1, __shfl_xor_sync(0xffffffffu, mx1, 1));
        mx1 = fmaxf(mx1, __shfl_xor_sync(0xffffffffu, mx1, 2));

        float mn0 = fmaxf(mi0, mx0), mn1 = fmaxf(mi1, mx1);
        float al0 = __expf(mi0 - mn0), al1 = __expf(mi1 - mn1);

        float sum0 = 0.0f, sum1 = 0.0f;
        #pragma unroll
        for (int nt = 0; nt < 8; nt++) {
            float p0 = __expf(sacc[nt][0] - mn0);
            float p1 = __expf(sacc[nt][1] - mn0);
            float p2 = __expf(sacc[nt][2] - mn1);
            float p3 = __expf(sacc[nt][3] - mn1);
            sum0 += p0 + p1;
            sum1 += p2 + p3;
            sacc[nt][0] = p0; sacc[nt][1] = p1;
            sacc[nt][2] = p2; sacc[nt][3] = p3;
        }
        sum0 += __shfl_xor_sync(0xffffffffu, sum0, 1);
        sum0 += __shfl_xor_sync(0xffffffffu, sum0, 2);
        sum1 += __shfl_xor_sync(0xffffffffu, sum1, 1);
        sum1 += __shfl_xor_sync(0xffffffffu, sum1, 2);

        li0 = li0 * al0 + sum0;  mi0 = mn0;
        li1 = li1 * al1 + sum1;  mi1 = mn1;
        #pragma unroll
        for (int nt = 0; nt < 8; nt++) {
            oacc[nt][0] *= al0; oacc[nt][1] *= al0;
            oacc[nt][2] *= al1; oacc[nt][3] *= al1;
        }

        // ---- stage P (tf32 bits) ----
        __syncwarp();
        #pragma unroll
        for (int nt = 0; nt < 8; nt++) {
            float2 p01, p23;
            p01.x = f2tf32f(sacc[nt][0]);
            p01.y = f2tf32f(sacc[nt][1]);
            p23.x = f2tf32f(sacc[nt][2]);
            p23.y = f2tf32f(sacc[nt][3]);
            *(float2*)(Ps + rowA * FSTR + nt * 8 + 2 * tq) = p01;
            *(float2*)(Ps + (rowA + 8) * FSTR + nt * 8 + 2 * tq) = p23;
        }
        __syncwarp();

        // ---- O += P V ----
        #pragma unroll
        for (int kc = 0; kc < 8; kc++) {
            uint32_t af[4];
            af[0] = __float_as_uint(Ps[rowA * FSTR + kc * 8 + tq]);
            af[1] = __float_as_uint(Ps[(rowA + 8) * FSTR + kc * 8 + tq]);
            af[2] = __float_as_uint(Ps[rowA * FSTR + kc * 8 + tq + 4]);
            af[3] = __float_as_uint(Ps[(rowA + 8) * FSTR + kc * 8 + tq + 4]);
            #pragma unroll
            for (int nt = 0; nt < 8; nt++) {
                uint32_t b0 = __float_as_uint(Vs[(kc * 8 + tq) * FSTR + nt * 8 + quad]);
                uint32_t b1 = __float_as_uint(Vs[(kc * 8 + tq + 4) * FSTR + nt * 8 + quad]);
                mma_tf32(oacc[nt], af, b0, b1);
            }
        }
    }

    // ---- epilogue: tf32-round (feeds proj gemm) ----
    const float inv0 = 1.0f / li0;
    const float inv1 = 1.0f / li1;
    const size_t r0 = (size_t)b * TT + q0 + w * 16 + quad;
    #pragma unroll
    for (int nt = 0; nt < 8; nt++) {
        const int col = h * HD + nt * 8 + 2 * tq;
        float2 v0, v1;
        v0.x = f2tf32f(oacc[nt][0] * inv0);  v0.y = f2tf32f(oacc[nt][1] * inv0);
        v1.x = f2tf32f(oacc[nt][2] * inv1);  v1.y = f2tf32f(oacc[nt][3] * inv1);
        *(float2*)(y + r0 * CC + col) = v0;
        *(float2*)(y + (r0 + 8) * CC + col) = v1;
    }
}

// ---------------------------------------------------------------------------
// Launch
// ---------------------------------------------------------------------------
extern "C" void kernel_launch(void* const* d_in, const int* in_sizes, int n_in,
                              void* d_out, int out_size)
{
    const float* x     = (const float*)d_in[0];
    const float* Wqkv  = (const float*)d_in[1];
    const float* bqkv  = (const float*)d_in[2];
    const float* Wproj = (const float*)d_in[3];
    const float* bproj = (const float*)d_in[4];
    float* out = (float*)d_out;

    float *qkv, *ybuf, *xt, *wt;
    cudaGetSymbolAddress((void**)&qkv, g_qkv);
    cudaGetSymbolAddress((void**)&ybuf, g_y);
    cudaGetSymbolAddress((void**)&xt, g_xt);
    cudaGetSymbolAddress((void**)&wt, g_wt);
    float* wqkv32  = wt;                     // [1024,3072] tf32-rounded
    float* wproj32 = wt + (size_t)CC * C3;   // [1024,1024] tf32-rounded

    const int smem_attn = 4 * 64 * FSTR * sizeof(float);   // 69632 B
    cudaFuncSetAttribute(flash_attn_mma,
                         cudaFuncAttributeMaxDynamicSharedMemorySize, smem_attn);

    // 0) tf32-round inputs/weights once.
    {
        int n4;
        n4 = (MM * CC) / 4;
        conv_tf32<<<(n4 + 255) / 256, 256>>>(x, xt, n4);
        n4 = (CC * C3) / 4;
        conv_tf32<<<(n4 + 255) / 256, 256>>>(Wqkv, wqkv32, n4);
        n4 = (CC * CC) / 4;
        conv_tf32<<<(n4 + 255) / 256, 256>>>(Wproj, wproj32, n4);
    }

    // 1) QKV projection (output tf32-rounded: feeds attention mma)
    gemm_tf32mma<true><<<dim3(C3 / BN, MM / BM), 256>>>(
        xt, wqkv32, bqkv, qkv, MM, C3, CC);

    // 2) Causal flash attention -> ybuf (tf32-rounded: feeds proj mma)
    flash_attn_mma<<<dim3(TT / BQ, HH, BB), 128, smem_attn>>>(qkv, ybuf);

    // 3) Output projection (final output: exact fp32)
    gemm_tf32mma<false><<<dim3(CC / BN, MM / BM), 256>>>(
        ybuf, wproj32, bproj, out, MM, CC, CC);
}

// round 6
// speedup vs baseline: 3.4935x; 1.1540x over previous
#include <cuda_runtime.h>
#include <math.h>
#include <stdint.h>

// Problem shape (fixed)
#define BB 4
#define TT 2048
#define CC 1024
#define HH 16
#define HD 64
#define MM (BB * TT)     // 8192 rows
#define C3 (3 * CC)      // 3072

// Scratch (device globals — allocation-free per harness rules)
__device__ float g_qkv[(size_t)MM * C3];   // 96 MB (tf32-rounded by QKV gemm)
__device__ float g_y[(size_t)MM * CC];     // 32 MB (tf32-rounded by attention)
__device__ float g_xt[(size_t)MM * CC];    // 32 MB x, tf32-rounded
__device__ float g_wt[(size_t)C3 * CC + (size_t)CC * CC];  // 16 MB weights, tf32-rounded

// ---------------------------------------------------------------------------
// PTX helpers (baseline sm_80+ only: harness PTX target is compute_103,
// which rejects tcgen05/accelerated-arch instructions).
// ---------------------------------------------------------------------------
__device__ __forceinline__ uint32_t smem_u32(const void* p) {
    uint32_t a;
    asm("{ .reg .u64 t; cvta.to.shared.u64 t, %1; cvt.u32.u64 %0, t; }"
        : "=r"(a) : "l"(p));
    return a;
}

#define CP_ASYNC16(dst, src) \
    asm volatile("cp.async.cg.shared.global [%0], [%1], 16;\n" \
                 :: "r"(dst), "l"(src) : "memory")
#define CP_COMMIT()  asm volatile("cp.async.commit_group;\n" ::: "memory")
#define CP_WAIT1()   asm volatile("cp.async.wait_group 1;\n" ::: "memory")

__device__ __forceinline__ uint32_t f2tf32(float f) {
    uint32_t r;
    asm("cvt.rna.tf32.f32 %0, %1;" : "=r"(r) : "f"(f));
    return r;
}
__device__ __forceinline__ float f2tf32f(float f) {
    return __uint_as_float(f2tf32(f));
}

__device__ __forceinline__ void mma_tf32(float c[4], const uint32_t a[4],
                                         uint32_t b0, uint32_t b1) {
    asm volatile(
        "mma.sync.aligned.m16n8k8.row.col.f32.tf32.tf32.f32 "
        "{%0,%1,%2,%3}, {%4,%5,%6,%7}, {%8,%9}, {%0,%1,%2,%3};"
        : "+f"(c[0]), "+f"(c[1]), "+f"(c[2]), "+f"(c[3])
        : "r"(a[0]), "r"(a[1]), "r"(a[2]), "r"(a[3]), "r"(b0), "r"(b1));
}

// ---------------------------------------------------------------------------
// Elementwise tf32 rounding pass.
// ---------------------------------------------------------------------------
__global__ __launch_bounds__(256)
void conv_tf32(const float* __restrict__ in, float* __restrict__ out, int n4)
{
    int i = blockIdx.x * 256 + threadIdx.x;
    if (i < n4) {
        float4 v = ((const float4*)in)[i];
        float4 o;
        o.x = f2tf32f(v.x); o.y = f2tf32f(v.y);
        o.z = f2tf32f(v.z); o.w = f2tf32f(v.w);
        ((float4*)out)[i] = o;
    }
}

// ---------------------------------------------------------------------------
// TF32 mma.sync GEMM: C = A @ B + bias. Operands pre-rounded to tf32.
// CTA 128x128x16, 128 threads (4 warps, 2x2), warp tile 64x64.
// 3-stage cp.async pipeline, ONE syncthreads per k-tile.
// A smem [m][k] stride 20, B smem [k][n] stride 136 (bank-bijective frags).
// ---------------------------------------------------------------------------
#define BM 128
#define BN 128
#define BK 16
#define ASTR 20
#define BSTR 136
#define NSTAGE 3
#define AS_SZ (BM * ASTR)   // 2560 floats
#define BS_SZ (BK * BSTR)   // 2176 floats

template<bool ROUND_OUT>
__global__ __launch_bounds__(128)
void gemm_tf32mma(const float* __restrict__ A, const float* __restrict__ B,
                  const float* __restrict__ bias, float* __restrict__ C,
                  int M, int N, int K)
{
    extern __shared__ float smd[];
    float* Asm = smd;                     // [NSTAGE][AS_SZ]
    float* Bsm = smd + NSTAGE * AS_SZ;    // [NSTAGE][BS_SZ]

    const int tid  = threadIdx.x;
    const int wid  = tid >> 5;
    const int lane = tid & 31;
    const int quad = lane >> 2;
    const int tq   = lane & 3;
    const int warpM = wid & 1;
    const int warpN = wid >> 1;
    const int row0 = blockIdx.y * BM;
    const int col0 = blockIdx.x * BN;

    float acc[4][8][4];
    #pragma unroll
    for (int mt = 0; mt < 4; mt++)
        #pragma unroll
        for (int nt = 0; nt < 8; nt++)
            #pragma unroll
            for (int j = 0; j < 4; j++) acc[mt][nt][j] = 0.0f;

    const uint32_t sAu = smem_u32(Asm);
    const uint32_t sBu = smem_u32(Bsm);

    auto load_tile = [&](int kt) {
        const int s = kt % NSTAGE;
        const int k0 = kt * BK;
        #pragma unroll
        for (int i = 0; i < 4; i++) {
            const int id  = tid + i * 128;
            const int ar  = id >> 2;
            const int akc = (id & 3) << 2;
            CP_ASYNC16(sAu + (uint32_t)(s * AS_SZ + ar * ASTR + akc) * 4,
                       A + (size_t)(row0 + ar) * K + k0 + akc);
            const int br  = id >> 5;
            const int bnc = (id & 31) << 2;
            CP_ASYNC16(sBu + (uint32_t)(s * BS_SZ + br * BSTR + bnc) * 4,
                       B + (size_t)(k0 + br) * N + col0 + bnc);
        }
        CP_COMMIT();
    };

    const int NKT = K / BK;
    load_tile(0);
    load_tile(1);

    for (int kt = 0; kt < NKT; kt++) {
        CP_WAIT1();          // stage kt complete (<=1 group pending)
        __syncthreads();     // all warps past reads of stage (kt-1)%3
        if (kt + 2 < NKT) load_tile(kt + 2);   // writes stage (kt+2)%3 == (kt-1)%3

        const float* as = Asm + (kt % NSTAGE) * AS_SZ;
        const float* bs = Bsm + (kt % NSTAGE) * BS_SZ;

        #pragma unroll
        for (int ks = 0; ks < 2; ks++) {
            uint32_t af[4][4];
            #pragma unroll
            for (int mt = 0; mt < 4; mt++) {
                const int mb = warpM * 64 + mt * 16 + quad;
                const int c  = ks * 8 + tq;
                af[mt][0] = __float_as_uint(as[mb * ASTR + c]);
                af[mt][1] = __float_as_uint(as[(mb + 8) * ASTR + c]);
                af[mt][2] = __float_as_uint(as[mb * ASTR + c + 4]);
                af[mt][3] = __float_as_uint(as[(mb + 8) * ASTR + c + 4]);
            }
            #pragma unroll
            for (int nt = 0; nt < 8; nt++) {
                const int n0 = warpN * 64 + nt * 8 + quad;
                uint32_t b0 = __float_as_uint(bs[(ks * 8 + tq) * BSTR + n0]);
                uint32_t b1 = __float_as_uint(bs[(ks * 8 + tq + 4) * BSTR + n0]);
                #pragma unroll
                for (int mt = 0; mt < 4; mt++)
                    mma_tf32(acc[mt][nt], af[mt], b0, b1);
            }
        }
    }

    // Epilogue
    #pragma unroll
    for (int mt = 0; mt < 4; mt++) {
        #pragma unroll
        for (int half = 0; half < 2; half++) {
            const int row = row0 + warpM * 64 + mt * 16 + quad + half * 8;
            float* crow = C + (size_t)row * N;
            #pragma unroll
            for (int nt = 0; nt < 8; nt++) {
                const int col = col0 + warpN * 64 + nt * 8 + 2 * tq;
                float2 v;
                v.x = acc[mt][nt][half * 2 + 0] + __ldg(bias + col);
                v.y = acc[mt][nt][half * 2 + 1] + __ldg(bias + col + 1);
                if (ROUND_OUT) { v.x = f2tf32f(v.x); v.y = f2tf32f(v.y); }
                *(float2*)(crow + col) = v;
            }
        }
    }
}

// ---------------------------------------------------------------------------
// Flash attention, tf32 mma.sync. BQ=128: block = 128 threads (4 warps),
// warp owns 32 q rows (2 m16 tiles). KV tiles of 64. qkv pre-rounded tf32.
// Per-warp exact causal handling: each warp masks exactly one kv tile and
// warps 0-1 skip the final (fully masked) tile.
// ---------------------------------------------------------------------------
#define FSTR 68
#define BQ 128

__global__ __launch_bounds__(128)
void flash_attn_mma(const float* __restrict__ qkv, float* __restrict__ y)
{
    extern __shared__ float sm[];
    float* Qs = sm;                    // [128][68]
    float* Ks = Qs + 128 * FSTR;       // [64][68]
    float* Vs = Ks + 64 * FSTR;        // [64][68]
    float* Ps = Vs + 64 * FSTR;        // [128][68]

    const int tid  = threadIdx.x;
    const int w    = tid >> 5;
    const int lane = tid & 31;
    const int quad = lane >> 2;
    const int tq   = lane & 3;

    const int b = blockIdx.z, h = blockIdx.y;
    const int q0 = (gridDim.x - 1 - blockIdx.x) * BQ;   // heavy tiles first

    const float* base = qkv + (size_t)b * TT * C3 + h * HD;
    const float* Qg = base;
    const float* Kg = base + CC;
    const float* Vg = base + 2 * CC;

    // Load Q tile (128 x 64, already tf32-rounded).
    #pragma unroll
    for (int it = 0; it < 16; it++) {
        int idx = tid + it * 128;
        int r  = idx >> 4;
        int dc = (idx & 15) << 2;
        *(float4*)(Qs + r * FSTR + dc) =
            *(const float4*)(Qg + (size_t)(q0 + r) * C3 + dc);
    }

    // Warp w, m-tile mt: rows w*32 + mt*16 + quad (+8).
    float mi[2][2], li[2][2];
    #pragma unroll
    for (int mt = 0; mt < 2; mt++) {
        mi[mt][0] = -1e30f; mi[mt][1] = -1e30f;
        li[mt][0] = 0.0f;   li[mt][1] = 0.0f;
    }
    float oacc[2][8][4];
    #pragma unroll
    for (int mt = 0; mt < 2; mt++)
        #pragma unroll
        for (int nt = 0; nt < 8; nt++)
            #pragma unroll
            for (int j = 0; j < 4; j++) oacc[mt][nt][j] = 0.0f;

    const int ntile = (q0 >> 6) + 2;
    for (int jt = 0; jt < ntile; jt++) {
        const int k0 = jt << 6;
        __syncthreads();

        // Load K and V tiles (64 x 64 each).
        #pragma unroll
        for (int it = 0; it < 8; it++) {
            int idx = tid + it * 128;
            int r  = idx >> 4;
            int dc = (idx & 15) << 2;
            *(float4*)(Ks + r * FSTR + dc) =
                *(const float4*)(Kg + (size_t)(k0 + r) * C3 + dc);
            *(float4*)(Vs + r * FSTR + dc) =
                *(const float4*)(Vg + (size_t)(k0 + r) * C3 + dc);
        }
        __syncthreads();

        // Warps 0,1 are entirely above the diagonal on the last tile: skip.
        if (jt == ntile - 1 && w < 2) continue;

        // This warp's diagonal-crossing tile:
        const bool diag = (w < 2) ? (jt == ntile - 2) : (jt == ntile - 1);

        // ---- S = Q K^T : warp computes 32 x 64 ----
        float sacc[2][8][4];
        #pragma unroll
        for (int mt = 0; mt < 2; mt++)
            #pragma unroll
            for (int nt = 0; nt < 8; nt++)
                #pragma unroll
                for (int j = 0; j < 4; j++) sacc[mt][nt][j] = 0.0f;

        #pragma unroll
        for (int kc = 0; kc < 8; kc++) {
            uint32_t af[2][4];
            #pragma unroll
            for (int mt = 0; mt < 2; mt++) {
                const int rowA = w * 32 + mt * 16 + quad;
                af[mt][0] = __float_as_uint(Qs[rowA * FSTR + kc * 8 + tq]);
                af[mt][1] = __float_as_uint(Qs[(rowA + 8) * FSTR + kc * 8 + tq]);
                af[mt][2] = __float_as_uint(Qs[rowA * FSTR + kc * 8 + tq + 4]);
                af[mt][3] = __float_as_uint(Qs[(rowA + 8) * FSTR + kc * 8 + tq + 4]);
            }
            #pragma unroll
            for (int nt = 0; nt < 8; nt++) {
                uint32_t b0 = __float_as_uint(Ks[(nt * 8 + quad) * FSTR + kc * 8 + tq]);
                uint32_t b1 = __float_as_uint(Ks[(nt * 8 + quad) * FSTR + kc * 8 + tq + 4]);
                mma_tf32(sacc[0][nt], af[0], b0, b1);
                mma_tf32(sacc[1][nt], af[1], b0, b1);
            }
        }

        // ---- scale + causal mask ----
        const float scale = 0.125f;
        #pragma unroll
        for (int mt = 0; mt < 2; mt++) {
            #pragma unroll
            for (int nt = 0; nt < 8; nt++) {
                #pragma unroll
                for (int j = 0; j < 4; j++) {
                    float v = sacc[mt][nt][j] * scale;
                    if (diag) {
                        int c = k0 + nt * 8 + 2 * tq + (j & 1);
                        int r = q0 + w * 32 + mt * 16 + quad + (j >> 1) * 8;
                        if (c > r) v = -1e30f;
                    }
                    sacc[mt][nt][j] = v;
                }
            }
        }

        // ---- online softmax (per mt: rows quad, quad+8; reduce over tq) ----
        #pragma unroll
        for (int mt = 0; mt < 2; mt++) {
            float mx0 = -1e30f, mx1 = -1e30f;
            #pragma unroll
            for (int nt = 0; nt < 8; nt++) {
                mx0 = fmaxf(mx0, fmaxf(sacc[mt][nt][0], sacc[mt][nt][1]));
                mx1 = fmaxf(mx1, fmaxf(sacc[mt][nt][2], sacc[mt][nt][3]));
            }
            mx0 = fmaxf(mx0, __shfl_xor_sync(0xffffffffu, mx0, 1));
            mx0 = fmaxf(mx0, __shfl_xor_sync(0xffffffffu, mx0, 2));
            mx1 = fmaxf(mx1, __shfl_xor_sync(0xffffffffu, mx1, 1));
            mx1 = fmaxf(mx1, __shfl_xor_sync(0xffffffffu, mx1, 2));

            float mn0 = fmaxf(mi[mt][0], mx0), mn1 = fmaxf(mi[mt][1], mx1);
            float al0 = __expf(mi[mt][0] - mn0), al1 = __expf(mi[mt][1] - mn1);

            float sum0 = 0.0f, sum1 = 0.0f;
            #pragma unroll
            for (int nt = 0; nt < 8; nt++) {
                float p0 = __expf(sacc[mt][nt][0] - mn0);
                float p1 = __expf(sacc[mt][nt][1] - mn0);
                float p2 = __expf(sacc[mt][nt][2] - mn1);
                float p3 = __expf(sacc[mt][nt][3] - mn1);
                sum0 += p0 + p1;
                sum1 += p2 + p3;
                sacc[mt][nt][0] = p0; sacc[mt][nt][1] = p1;
                sacc[mt][nt][2] = p2; sacc[mt][nt][3] = p3;
            }
            sum0 += __shfl_xor_sync(0xffffffffu, sum0, 1);
            sum0 += __shfl_xor_sync(0xffffffffu, sum0, 2);
            sum1 += __shfl_xor_sync(0xffffffffu, sum1, 1);
            sum1 += __shfl_xor_sync(0xffffffffu, sum1, 2);

            li[mt][0] = li[mt][0] * al0 + sum0;  mi[mt][0] = mn0;
            li[mt][1] = li[mt][1] * al1 + sum1;  mi[mt][1] = mn1;
            #pragma unroll
            for (int nt = 0; nt < 8; nt++) {
                oacc[mt][nt][0] *= al0; oacc[mt][nt][1] *= al0;
                oacc[mt][nt][2] *= al1; oacc[mt][nt][3] *= al1;
            }
        }

        // ---- stage P (tf32 bits) into warp-private rows ----
        __syncwarp();
        #pragma unroll
        for (int mt = 0; mt < 2; mt++) {
            const int rowA = w * 32 + mt * 16 + quad;
            #pragma unroll
            for (int nt = 0; nt < 8; nt++) {
                float2 p01, p23;
                p01.x = f2tf32f(sacc[mt][nt][0]);
                p01.y = f2tf32f(sacc[mt][nt][1]);
                p23.x = f2tf32f(sacc[mt][nt][2]);
                p23.y = f2tf32f(sacc[mt][nt][3]);
                *(float2*)(Ps + rowA * FSTR + nt * 8 + 2 * tq) = p01;
                *(float2*)(Ps + (rowA + 8) * FSTR + nt * 8 + 2 * tq) = p23;
            }
        }
        __syncwarp();

        // ---- O += P V ----
        #pragma unroll
        for (int kc = 0; kc < 8; kc++) {
            uint32_t af[2][4];
            #pragma unroll
            for (int mt = 0; mt < 2; mt++) {
                const int rowA = w * 32 + mt * 16 + quad;
                af[mt][0] = __float_as_uint(Ps[rowA * FSTR + kc * 8 + tq]);
                af[mt][1] = __float_as_uint(Ps[(rowA + 8) * FSTR + kc * 8 + tq]);
                af[mt][2] = __float_as_uint(Ps[rowA * FSTR + kc * 8 + tq + 4]);
                af[mt][3] = __float_as_uint(Ps[(rowA + 8) * FSTR + kc * 8 + tq + 4]);
            }
            #pragma unroll
            for (int nt = 0; nt < 8; nt++) {
                uint32_t b0 = __float_as_uint(Vs[(kc * 8 + tq) * FSTR + nt * 8 + quad]);
                uint32_t b1 = __float_as_uint(Vs[(kc * 8 + tq + 4) * FSTR + nt * 8 + quad]);
                mma_tf32(oacc[0][nt], af[0], b0, b1);
                mma_tf32(oacc[1][nt], af[1], b0, b1);
            }
        }
    }

    // ---- epilogue: tf32-round (feeds proj gemm) ----
    #pragma unroll
    for (int mt = 0; mt < 2; mt++) {
        const float inv0 = 1.0f / li[mt][0];
        const float inv1 = 1.0f / li[mt][1];
        const size_t r0 = (size_t)b * TT + q0 + w * 32 + mt * 16 + quad;
        #pragma unroll
        for (int nt = 0; nt < 8; nt++) {
            const int col = h * HD + nt * 8 + 2 * tq;
            float2 v0, v1;
            v0.x = f2tf32f(oacc[mt][nt][0] * inv0);
            v0.y = f2tf32f(oacc[mt][nt][1] * inv0);
            v1.x = f2tf32f(oacc[mt][nt][2] * inv1);
            v1.y = f2tf32f(oacc[mt][nt][3] * inv1);
            *(float2*)(y + r0 * CC + col) = v0;
            *(float2*)(y + (r0 + 8) * CC + col) = v1;
        }
    }
}

// ---------------------------------------------------------------------------
// Launch
// ---------------------------------------------------------------------------
extern "C" void kernel_launch(void* const* d_in, const int* in_sizes, int n_in,
                              void* d_out, int out_size)
{
    const float* x     = (const float*)d_in[0];
    const float* Wqkv  = (const float*)d_in[1];
    const float* bqkv  = (const float*)d_in[2];
    const float* Wproj = (const float*)d_in[3];
    const float* bproj = (const float*)d_in[4];
    float* out = (float*)d_out;

    float *qkv, *ybuf, *xt, *wt;
    cudaGetSymbolAddress((void**)&qkv, g_qkv);
    cudaGetSymbolAddress((void**)&ybuf, g_y);
    cudaGetSymbolAddress((void**)&xt, g_xt);
    cudaGetSymbolAddress((void**)&wt, g_wt);
    float* wqkv32  = wt;
    float* wproj32 = wt + (size_t)CC * C3;

    const int smem_gemm = NSTAGE * (AS_SZ + BS_SZ) * sizeof(float);   // 56832
    cudaFuncSetAttribute(gemm_tf32mma<true>,
                         cudaFuncAttributeMaxDynamicSharedMemorySize, smem_gemm);
    cudaFuncSetAttribute(gemm_tf32mma<false>,
                         cudaFuncAttributeMaxDynamicSharedMemorySize, smem_gemm);

    const int smem_attn = (128 + 64 + 64 + 128) * FSTR * sizeof(float);  // 104448
    cudaFuncSetAttribute(flash_attn_mma,
                         cudaFuncAttributeMaxDynamicSharedMemorySize, smem_attn);

    // 0) tf32-round inputs/weights once.
    {
        int n4;
        n4 = (MM * CC) / 4;
        conv_tf32<<<(n4 + 255) / 256, 256>>>(x, xt, n4);
        n4 = (CC * C3) / 4;
        conv_tf32<<<(n4 + 255) / 256, 256>>>(Wqkv, wqkv32, n4);
        n4 = (CC * CC) / 4;
        conv_tf32<<<(n4 + 255) / 256, 256>>>(Wproj, wproj32, n4);
    }

    // 1) QKV projection (output tf32-rounded: feeds attention mma)
    gemm_tf32mma<true><<<dim3(C3 / BN, MM / BM), 128, smem_gemm>>>(
        xt, wqkv32, bqkv, qkv, MM, C3, CC);

    // 2) Causal flash attention -> ybuf (tf32-rounded: feeds proj mma)
    flash_attn_mma<<<dim3(TT / BQ, HH, BB), 128, smem_attn>>>(qkv, ybuf);

    // 3) Output projection (final output: exact fp32)
    gemm_tf32mma<false><<<dim3(CC / BN, MM / BM), 128, smem_gemm>>>(
        ybuf, wproj32, bproj, out, MM, CC, CC);
}

// round 8
// speedup vs baseline: 3.5812x; 1.0251x over previous
#include <cuda_runtime.h>
#include <math.h>
#include <stdint.h>

// Problem shape (fixed)
#define BB 4
#define TT 2048
#define CC 1024
#define HH 16
#define HD 64
#define MM (BB * TT)     // 8192 rows
#define C3 (3 * CC)      // 3072

// Scratch (device globals — allocation-free per harness rules)
__device__ float g_qkv[(size_t)MM * C3];   // 96 MB (tf32-rounded by QKV gemm)
__device__ float g_y[(size_t)MM * CC];     // 32 MB (tf32-rounded by attention)
__device__ float g_xt[(size_t)MM * CC];    // 32 MB x, tf32-rounded
__device__ float g_wt[(size_t)C3 * CC + (size_t)CC * CC];  // 16 MB weights, tf32-rounded

// ---------------------------------------------------------------------------
// PTX helpers (baseline sm_80+ only: harness PTX target is compute_103,
// which rejects tcgen05/accelerated-arch instructions).
// ---------------------------------------------------------------------------
#define CP_ASYNC16(dst, src) \
    asm volatile("cp.async.cg.shared.global [%0], [%1], 16;\n" \
                 :: "r"(dst), "l"(src) : "memory")
#define CP_COMMIT()  asm volatile("cp.async.commit_group;\n" ::: "memory")
#define CP_WAIT1()   asm volatile("cp.async.wait_group 1;\n" ::: "memory")

__device__ __forceinline__ uint32_t smem_u32(const void* p) {
    uint32_t a;
    asm("{ .reg .u64 t; cvta.to.shared.u64 t, %1; cvt.u32.u64 %0, t; }"
        : "=r"(a) : "l"(p));
    return a;
}

__device__ __forceinline__ uint32_t f2tf32(float f) {
    uint32_t r;
    asm("cvt.rna.tf32.f32 %0, %1;" : "=r"(r) : "f"(f));
    return r;
}
__device__ __forceinline__ float f2tf32f(float f) {
    return __uint_as_float(f2tf32(f));
}

__device__ __forceinline__ void mma_tf32(float c[4], const uint32_t a[4],
                                         uint32_t b0, uint32_t b1) {
    asm volatile(
        "mma.sync.aligned.m16n8k8.row.col.f32.tf32.tf32.f32 "
        "{%0,%1,%2,%3}, {%4,%5,%6,%7}, {%8,%9}, {%0,%1,%2,%3};"
        : "+f"(c[0]), "+f"(c[1]), "+f"(c[2]), "+f"(c[3])
        : "r"(a[0]), "r"(a[1]), "r"(a[2]), "r"(a[3]), "r"(b0), "r"(b1));
}

// ---------------------------------------------------------------------------
// Elementwise tf32 rounding pass.
// ---------------------------------------------------------------------------
__global__ __launch_bounds__(256)
void conv_tf32(const float* __restrict__ in, float* __restrict__ out, int n4)
{
    int i = blockIdx.x * 256 + threadIdx.x;
    if (i < n4) {
        float4 v = ((const float4*)in)[i];
        float4 o;
        o.x = f2tf32f(v.x); o.y = f2tf32f(v.y);
        o.z = f2tf32f(v.z); o.w = f2tf32f(v.w);
        ((float4*)out)[i] = o;
    }
}

// ---------------------------------------------------------------------------
// TF32 mma.sync GEMM: C = A @ B + bias. Operands pre-rounded to tf32.
// CTA 128x128x32, 128 threads (4 warps, 2x2), warp tile 64x64.
// 3-stage cp.async pipeline, ONE syncthreads per 32-wide k-tile (32 total).
// A smem [m][k] stride 36, B smem [k][n] stride 136 (bank-bijective frags).
// ---------------------------------------------------------------------------
#define BM 128
#define BN 128
#define BK 32
#define ASTR 36
#define BSTR 136
#define NSTAGE 3
#define AS_SZ (BM * ASTR)   // 4608 floats
#define BS_SZ (BK * BSTR)   // 4352 floats

template<bool ROUND_OUT>
__global__ __launch_bounds__(128)
void gemm_tf32mma(const float* __restrict__ A, const float* __restrict__ B,
                  const float* __restrict__ bias, float* __restrict__ C,
                  int M, int N, int K)
{
    extern __shared__ float smd[];
    float* Asm = smd;                     // [NSTAGE][AS_SZ]
    float* Bsm = smd + NSTAGE * AS_SZ;    // [NSTAGE][BS_SZ]

    const int tid  = threadIdx.x;
    const int wid  = tid >> 5;
    const int lane = tid & 31;
    const int quad = lane >> 2;
    const int tq   = lane & 3;
    const int warpM = wid & 1;
    const int warpN = wid >> 1;
    const int row0 = blockIdx.y * BM;
    const int col0 = blockIdx.x * BN;

    float acc[4][8][4];
    #pragma unroll
    for (int mt = 0; mt < 4; mt++)
        #pragma unroll
        for (int nt = 0; nt < 8; nt++)
            #pragma unroll
            for (int j = 0; j < 4; j++) acc[mt][nt][j] = 0.0f;

    const uint32_t sAu = smem_u32(Asm);
    const uint32_t sBu = smem_u32(Bsm);

    auto load_tile = [&](int kt) {
        const int s = kt % NSTAGE;
        const int k0 = kt * BK;
        #pragma unroll
        for (int i = 0; i < 8; i++) {
            const int id  = tid + i * 128;
            const int ar  = id >> 3;             // 0..127
            const int akc = (id & 7) << 2;       // 0..28
            CP_ASYNC16(sAu + (uint32_t)(s * AS_SZ + ar * ASTR + akc) * 4,
                       A + (size_t)(row0 + ar) * K + k0 + akc);
            const int br  = id >> 5;             // 0..31
            const int bnc = (id & 31) << 2;      // 0..124
            CP_ASYNC16(sBu + (uint32_t)(s * BS_SZ + br * BSTR + bnc) * 4,
                       B + (size_t)(k0 + br) * N + col0 + bnc);
        }
        CP_COMMIT();
    };

    const int NKT = K / BK;   // 32
    load_tile(0);
    load_tile(1);

    for (int kt = 0; kt < NKT; kt++) {
        CP_WAIT1();          // stage kt complete (<=1 group pending)
        __syncthreads();     // all warps past reads of stage (kt-1)%3
        if (kt + 2 < NKT) load_tile(kt + 2);   // refills freed stage

        const float* as = Asm + (kt % NSTAGE) * AS_SZ;
        const float* bs = Bsm + (kt % NSTAGE) * BS_SZ;

        #pragma unroll
        for (int ks = 0; ks < 4; ks++) {
            uint32_t af[4][4];
            #pragma unroll
            for (int mt = 0; mt < 4; mt++) {
                const int mb = warpM * 64 + mt * 16 + quad;
                const int c  = ks * 8 + tq;
                af[mt][0] = __float_as_uint(as[mb * ASTR + c]);
                af[mt][1] = __float_as_uint(as[(mb + 8) * ASTR + c]);
                af[mt][2] = __float_as_uint(as[mb * ASTR + c + 4]);
                af[mt][3] = __float_as_uint(as[(mb + 8) * ASTR + c + 4]);
            }
            #pragma unroll
            for (int nt = 0; nt < 8; nt++) {
                const int n0 = warpN * 64 + nt * 8 + quad;
                uint32_t b0 = __float_as_uint(bs[(ks * 8 + tq) * BSTR + n0]);
                uint32_t b1 = __float_as_uint(bs[(ks * 8 + tq + 4) * BSTR + n0]);
                #pragma unroll
                for (int mt = 0; mt < 4; mt++)
                    mma_tf32(acc[mt][nt], af[mt], b0, b1);
            }
        }
    }

    // Epilogue
    #pragma unroll
    for (int mt = 0; mt < 4; mt++) {
        #pragma unroll
        for (int half = 0; half < 2; half++) {
            const int row = row0 + warpM * 64 + mt * 16 + quad + half * 8;
            float* crow = C + (size_t)row * N;
            #pragma unroll
            for (int nt = 0; nt < 8; nt++) {
                const int col = col0 + warpN * 64 + nt * 8 + 2 * tq;
                float2 v;
                v.x = acc[mt][nt][half * 2 + 0] + __ldg(bias + col);
                v.y = acc[mt][nt][half * 2 + 1] + __ldg(bias + col + 1);
                if (ROUND_OUT) { v.x = f2tf32f(v.x); v.y = f2tf32f(v.y); }
                *(float2*)(crow + col) = v;
            }
        }
    }
}

// ---------------------------------------------------------------------------
// Flash attention, tf32 mma.sync. BQ=128: block = 128 threads (4 warps),
// warp owns 32 q rows (2 m16 tiles). KV tiles of 64. qkv pre-rounded tf32.
// Dedicated P buffer (128 rows — R7's 64-row alias clobbered V).
// Smem 104448 B; forced 2 CTAs/SM (2x104448 <= 227KB).
// ---------------------------------------------------------------------------
#define FSTR 68
#define BQ 128

__global__ __launch_bounds__(128, 2)
void flash_attn_mma(const float* __restrict__ qkv, float* __restrict__ y)
{
    extern __shared__ float sm[];
    float* Qs = sm;                    // [128][68]
    float* Ks = Qs + 128 * FSTR;       // [64][68]
    float* Vs = Ks + 64 * FSTR;        // [64][68]
    float* Ps = Vs + 64 * FSTR;        // [128][68]

    const int tid  = threadIdx.x;
    const int w    = tid >> 5;
    const int lane = tid & 31;
    const int quad = lane >> 2;
    const int tq   = lane & 3;

    const int b = blockIdx.z, h = blockIdx.y;
    const int q0 = (gridDim.x - 1 - blockIdx.x) * BQ;   // heavy tiles first

    const float* base = qkv + (size_t)b * TT * C3 + h * HD;
    const float* Qg = base;
    const float* Kg = base + CC;
    const float* Vg = base + 2 * CC;

    // Load Q tile (128 x 64, already tf32-rounded).
    #pragma unroll
    for (int it = 0; it < 16; it++) {
        int idx = tid + it * 128;
        int r  = idx >> 4;
        int dc = (idx & 15) << 2;
        *(float4*)(Qs + r * FSTR + dc) =
            *(const float4*)(Qg + (size_t)(q0 + r) * C3 + dc);
    }

    float mi[2][2], li[2][2];
    #pragma unroll
    for (int mt = 0; mt < 2; mt++) {
        mi[mt][0] = -1e30f; mi[mt][1] = -1e30f;
        li[mt][0] = 0.0f;   li[mt][1] = 0.0f;
    }
    float oacc[2][8][4];
    #pragma unroll
    for (int mt = 0; mt < 2; mt++)
        #pragma unroll
        for (int nt = 0; nt < 8; nt++)
            #pragma unroll
            for (int j = 0; j < 4; j++) oacc[mt][nt][j] = 0.0f;

    const int ntile = (q0 >> 6) + 2;
    for (int jt = 0; jt < ntile; jt++) {
        const int k0 = jt << 6;
        __syncthreads();   // prev-iter K/V/P reads complete before overwrite

        // Load K and V tiles (64 x 64 each).
        #pragma unroll
        for (int it = 0; it < 8; it++) {
            int idx = tid + it * 128;
            int r  = idx >> 4;
            int dc = (idx & 15) << 2;
            *(float4*)(Ks + r * FSTR + dc) =
                *(const float4*)(Kg + (size_t)(k0 + r) * C3 + dc);
            *(float4*)(Vs + r * FSTR + dc) =
                *(const float4*)(Vg + (size_t)(k0 + r) * C3 + dc);
        }
        __syncthreads();

        // Warps 0,1 are fully masked on the last tile: skip compute entirely.
        if (jt == ntile - 1 && w < 2) continue;

        const bool diag = (w < 2) ? (jt == ntile - 2) : (jt == ntile - 1);

        // ---- S = Q K^T : warp computes 32 x 64 ----
        float sacc[2][8][4];
        #pragma unroll
        for (int mt = 0; mt < 2; mt++)
            #pragma unroll
            for (int nt = 0; nt < 8; nt++)
                #pragma unroll
                for (int j = 0; j < 4; j++) sacc[mt][nt][j] = 0.0f;

        #pragma unroll
        for (int kc = 0; kc < 8; kc++) {
            uint32_t af[2][4];
            #pragma unroll
            for (int mt = 0; mt < 2; mt++) {
                const int rowA = w * 32 + mt * 16 + quad;
                af[mt][0] = __float_as_uint(Qs[rowA * FSTR + kc * 8 + tq]);
                af[mt][1] = __float_as_uint(Qs[(rowA + 8) * FSTR + kc * 8 + tq]);
                af[mt][2] = __float_as_uint(Qs[rowA * FSTR + kc * 8 + tq + 4]);
                af[mt][3] = __float_as_uint(Qs[(rowA + 8) * FSTR + kc * 8 + tq + 4]);
            }
            #pragma unroll
            for (int nt = 0; nt < 8; nt++) {
                uint32_t b0 = __float_as_uint(Ks[(nt * 8 + quad) * FSTR + kc * 8 + tq]);
                uint32_t b1 = __float_as_uint(Ks[(nt * 8 + quad) * FSTR + kc * 8 + tq + 4]);
                mma_tf32(sacc[0][nt], af[0], b0, b1);
                mma_tf32(sacc[1][nt], af[1], b0, b1);
            }
        }

        // ---- scale + causal mask ----
        const float scale = 0.125f;
        #pragma unroll
        for (int mt = 0; mt < 2; mt++) {
            #pragma unroll
            for (int nt = 0; nt < 8; nt++) {
                #pragma unroll
                for (int j = 0; j < 4; j++) {
                    float v = sacc[mt][nt][j] * scale;
                    if (diag) {
                        int c = k0 + nt * 8 + 2 * tq + (j & 1);
                        int r = q0 + w * 32 + mt * 16 + quad + (j >> 1) * 8;
                        if (c > r) v = -1e30f;
                    }
                    sacc[mt][nt][j] = v;
                }
            }
        }

        // ---- online softmax (per mt: rows quad, quad+8; reduce over tq) ----
        #pragma unroll
        for (int mt = 0; mt < 2; mt++) {
            float mx0 = -1e30f, mx1 = -1e30f;
            #pragma unroll
            for (int nt = 0; nt < 8; nt++) {
                mx0 = fmaxf(mx0, fmaxf(sacc[mt][nt][0], sacc[mt][nt][1]));
                mx1 = fmaxf(mx1, fmaxf(sacc[mt][nt][2], sacc[mt][nt][3]));
            }
            mx0 = fmaxf(mx0, __shfl_xor_sync(0xffffffffu, mx0, 1));
            mx0 = fmaxf(mx0, __shfl_xor_sync(0xffffffffu, mx0, 2));
            mx1 = fmaxf(mx1, __shfl_xor_sync(0xffffffffu, mx1, 1));
            mx1 = fmaxf(mx1, __shfl_xor_sync(0xffffffffu, mx1, 2));

            float mn0 = fmaxf(mi[mt][0], mx0), mn1 = fmaxf(mi[mt][1], mx1);
            float al0 = __expf(mi[mt][0] - mn0), al1 = __expf(mi[mt][1] - mn1);

            float sum0 = 0.0f, sum1 = 0.0f;
            #pragma unroll
            for (int nt = 0; nt < 8; nt++) {
                float p0 = __expf(sacc[mt][nt][0] - mn0);
                float p1 = __expf(sacc[mt][nt][1] - mn0);
                float p2 = __expf(sacc[mt][nt][2] - mn1);
                float p3 = __expf(sacc[mt][nt][3] - mn1);
                sum0 += p0 + p1;
                sum1 += p2 + p3;
                sacc[mt][nt][0] = p0; sacc[mt][nt][1] = p1;
                sacc[mt][nt][2] = p2; sacc[mt][nt][3] = p3;
            }
            sum0 += __shfl_xor_sync(0xffffffffu, sum0, 1);
            sum0 += __shfl_xor_sync(0xffffffffu, sum0, 2);
            sum1 += __shfl_xor_sync(0xffffffffu, sum1, 1);
            sum1 += __shfl_xor_sync(0xffffffffu, sum1, 2);

            li[mt][0] = li[mt][0] * al0 + sum0;  mi[mt][0] = mn0;
            li[mt][1] = li[mt][1] * al1 + sum1;  mi[mt][1] = mn1;
            #pragma unroll
            for (int nt = 0; nt < 8; nt++) {
                oacc[mt][nt][0] *= al0; oacc[mt][nt][1] *= al0;
                oacc[mt][nt][2] *= al1; oacc[mt][nt][3] *= al1;
            }
        }

        // ---- stage P (tf32 bits) into warp-private rows ----
        __syncwarp();
        #pragma unroll
        for (int mt = 0; mt < 2; mt++) {
            const int rowA = w * 32 + mt * 16 + quad;
            #pragma unroll
            for (int nt = 0; nt < 8; nt++) {
                float2 p01, p23;
                p01.x = f2tf32f(sacc[mt][nt][0]);
                p01.y = f2tf32f(sacc[mt][nt][1]);
                p23.x = f2tf32f(sacc[mt][nt][2]);
                p23.y = f2tf32f(sacc[mt][nt][3]);
                *(float2*)(Ps + rowA * FSTR + nt * 8 + 2 * tq) = p01;
                *(float2*)(Ps + (rowA + 8) * FSTR + nt * 8 + 2 * tq) = p23;
            }
        }
        __syncwarp();

        // ---- O += P V ----
        #pragma unroll
        for (int kc = 0; kc < 8; kc++) {
            uint32_t af[2][4];
            #pragma unroll
            for (int mt = 0; mt < 2; mt++) {
                const int rowA = w * 32 + mt * 16 + quad;
                af[mt][0] = __float_as_uint(Ps[rowA * FSTR + kc * 8 + tq]);
                af[mt][1] = __float_as_uint(Ps[(rowA + 8) * FSTR + kc * 8 + tq]);
                af[mt][2] = __float_as_uint(Ps[rowA * FSTR + kc * 8 + tq + 4]);
                af[mt][3] = __float_as_uint(Ps[(rowA + 8) * FSTR + kc * 8 + tq + 4]);
            }
            #pragma unroll
            for (int nt = 0; nt < 8; nt++) {
                uint32_t b0 = __float_as_uint(Vs[(kc * 8 + tq) * FSTR + nt * 8 + quad]);
                uint32_t b1 = __float_as_uint(Vs[(kc * 8 + tq + 4) * FSTR + nt * 8 + quad]);
                mma_tf32(oacc[0][nt], af[0], b0, b1);
                mma_tf32(oacc[1][nt], af[1], b0, b1);
            }
        }
    }

    // ---- epilogue: tf32-round (feeds proj gemm) ----
    #pragma unroll
    for (int mt = 0; mt < 2; mt++) {
        const float inv0 = 1.0f / li[mt][0];
        const float inv1 = 1.0f / li[mt][1];
        const size_t r0 = (size_t)b * TT + q0 + w * 32 + mt * 16 + quad;
        #pragma unroll
        for (int nt = 0; nt < 8; nt++) {
            const int col = h * HD + nt * 8 + 2 * tq;
            float2 v0, v1;
            v0.x = f2tf32f(oacc[mt][nt][0] * inv0);
            v0.y = f2tf32f(oacc[mt][nt][1] * inv0);
            v1.x = f2tf32f(oacc[mt][nt][2] * inv1);
            v1.y = f2tf32f(oacc[mt][nt][3] * inv1);
            *(float2*)(y + r0 * CC + col) = v0;
            *(float2*)(y + (r0 + 8) * CC + col) = v1;
        }
    }
}

// ---------------------------------------------------------------------------
// Launch
// ---------------------------------------------------------------------------
extern "C" void kernel_launch(void* const* d_in, const int* in_sizes, int n_in,
                              void* d_out, int out_size)
{
    const float* x     = (const float*)d_in[0];
    const float* Wqkv  = (const float*)d_in[1];
    const float* bqkv  = (const float*)d_in[2];
    const float* Wproj = (const float*)d_in[3];
    const float* bproj = (const float*)d_in[4];
    float* out = (float*)d_out;

    float *qkv, *ybuf, *xt, *wt;
    cudaGetSymbolAddress((void**)&qkv, g_qkv);
    cudaGetSymbolAddress((void**)&ybuf, g_y);
    cudaGetSymbolAddress((void**)&xt, g_xt);
    cudaGetSymbolAddress((void**)&wt, g_wt);
    float* wqkv32  = wt;
    float* wproj32 = wt + (size_t)CC * C3;

    const int smem_gemm = NSTAGE * (AS_SZ + BS_SZ) * sizeof(float);   // 107520
    cudaFuncSetAttribute(gemm_tf32mma<true>,
                         cudaFuncAttributeMaxDynamicSharedMemorySize, smem_gemm);
    cudaFuncSetAttribute(gemm_tf32mma<false>,
                         cudaFuncAttributeMaxDynamicSharedMemorySize, smem_gemm);

    const int smem_attn = (128 + 64 + 64 + 128) * FSTR * sizeof(float);  // 104448
    cudaFuncSetAttribute(flash_attn_mma,
                         cudaFuncAttributeMaxDynamicSharedMemorySize, smem_attn);

    // 0) tf32-round inputs/weights once.
    {
        int n4;
        n4 = (MM * CC) / 4;
        conv_tf32<<<(n4 + 255) / 256, 256>>>(x, xt, n4);
        n4 = (CC * C3) / 4;
        conv_tf32<<<(n4 + 255) / 256, 256>>>(Wqkv, wqkv32, n4);
        n4 = (CC * CC) / 4;
        conv_tf32<<<(n4 + 255) / 256, 256>>>(Wproj, wproj32, n4);
    }

    // 1) QKV projection (output tf32-rounded: feeds attention mma)
    gemm_tf32mma<true><<<dim3(C3 / BN, MM / BM), 128, smem_gemm>>>(
        xt, wqkv32, bqkv, qkv, MM, C3, CC);

    // 2) Causal flash attention -> ybuf (tf32-rounded: feeds proj mma)
    flash_attn_mma<<<dim3(TT / BQ, HH, BB), 128, smem_attn>>>(qkv, ybuf);

    // 3) Output projection (final output: exact fp32)
    gemm_tf32mma<false><<<dim3(CC / BN, MM / BM), 128, smem_gemm>>>(
        ybuf, wproj32, bproj, out, MM, CC, CC);
}